// round 3
// baseline (speedup 1.0000x reference)
#include <cuda_runtime.h>
#include <cstdint>

#define Bdim 256
#define Ddim 128
#define Cdim 8000
#define CPAD 8064
#define SCALE_F 64.0f
#define MARGIN_F 0.5f
#define EPS_F 1e-12f

#define BT 64
#define CT 128
#define KH 64   // K half per staging phase

// ---------------- device scratch (no allocations allowed) ----------------
__device__ float g_invn[CPAD];              // 1/||w_col||, zero for pad cols
__device__ float2 g_neT2[Ddim * Bdim];      // normalized embds, duplicated (v,v), [d][b]
__device__ float2 g_grT2[Ddim * Bdim];      // gathered label cols, duplicated, [d][b]
__device__ float g_s[Bdim];                 // s[b] = ne[b] . gr[b]
__device__ float g_rowsum[Bdim];            // softmax denominators

// ---------------- f32x2 helpers ----------------
__device__ __forceinline__ void ffma2(unsigned long long& d,
                                      unsigned long long a,
                                      unsigned long long b) {
    asm("fma.rn.f32x2 %0, %1, %2, %0;" : "+l"(d) : "l"(a), "l"(b));
}
__device__ __forceinline__ float2 unpack2(unsigned long long v) {
    float2 f;
    asm("mov.b64 {%0, %1}, %2;" : "=f"(f.x), "=f"(f.y) : "l"(v));
    return f;
}

// ---------------- K1: column inverse norms of w ----------------
__global__ void k_rnorm(const float* __restrict__ w) {
    int c = blockIdx.x * 256 + threadIdx.x;
    if (c >= CPAD) return;
    float r = 0.f;
    if (c < Cdim) {
        float ss = 0.f;
#pragma unroll 8
        for (int d = 0; d < Ddim; d++) {
            float v = w[d * Cdim + c];
            ss = fmaf(v, v, ss);
        }
        r = rsqrtf(fmaxf(ss, EPS_F));
    }
    g_invn[c] = r;
}

// ---------------- K2: normalize embds, gather gr (duplicated), compute s ----
__global__ void k_prep(const float* __restrict__ embds,
                       const float* __restrict__ w,
                       const int* __restrict__ labels) {
    int b = blockIdx.x;
    int d = threadIdx.x;  // 128 threads
    __shared__ float redA[4];
    __shared__ float redB[4];

    float e = embds[b * Ddim + d];
    float v = e * e;
#pragma unroll
    for (int o = 16; o > 0; o >>= 1) v += __shfl_xor_sync(0xffffffffu, v, o);
    if ((d & 31) == 0) redA[d >> 5] = v;
    __syncthreads();
    float ss = redA[0] + redA[1] + redA[2] + redA[3];
    float r = rsqrtf(fmaxf(ss, EPS_F));
    float ne = e * r;

    int lb = labels[b];
    float gr = w[d * Cdim + lb] * g_invn[lb];

    g_neT2[d * Bdim + b] = make_float2(ne, ne);
    g_grT2[d * Bdim + b] = make_float2(gr, gr);

    float sv = ne * gr;
#pragma unroll
    for (int o = 16; o > 0; o >>= 1) sv += __shfl_xor_sync(0xffffffffu, sv, o);
    if ((d & 31) == 0) redB[d >> 5] = sv;
    __syncthreads();
    if (d == 0) {
        g_s[b] = redB[0] + redB[1] + redB[2] + redB[3];
        g_rowsum[b] = 0.f;
    }
}

// ---------------- K3: fused dual GEMM + penalty + exp epilogue --------------
// smem per phase: sNw[64][128] 32KB + sNe2[64][64]f2 32KB + sGr2 32KB = 96KB
// -> 2 CTAs/SM resident (192KB).
__global__ __launch_bounds__(256, 2) void k_main(float* __restrict__ out,
                                                 const float* __restrict__ w,
                                                 const int* __restrict__ labels) {
    extern __shared__ float smem[];
    float* sNw = smem;                          // [k][c]   KH*CT floats
    float2* sNe2 = (float2*)(smem + KH * CT);   // [k][b] duplicated
    float2* sGr2 = sNe2 + KH * BT;

    const int tid = threadIdx.x;
    const int cBase = blockIdx.x * CT;
    const int bBase = blockIdx.y * BT;

    const int tx = tid & 15;   // c group
    const int ty = tid >> 4;   // b group

    float4* sNw4 = (float4*)sNw;
    float4* sNe4 = (float4*)sNe2;
    float4* sGr4 = (float4*)sGr2;
    const float4* gNe4 = (const float4*)g_neT2;  // row d: 128 float4
    const float4* gGr4 = (const float4*)g_grT2;

    unsigned long long accC[4][4];
    unsigned long long accG[4][4];
#pragma unroll
    for (int i = 0; i < 4; i++)
#pragma unroll
        for (int j = 0; j < 4; j++) { accC[i][j] = 0ull; accG[i][j] = 0ull; }

#pragma unroll
    for (int ph = 0; ph < 2; ph++) {
        if (ph) __syncthreads();   // previous-phase consumers done
        // ---- stage w * invn ----
#pragma unroll
        for (int i = 0; i < 8; i++) {
            int f = tid + i * 256;            // 2048 float4: 64 k x 32
            int k = f >> 5;
            int co = (f & 31) << 2;
            int c = cBase + co;
            int cw = c > Cdim - 4 ? Cdim - 4 : c;   // clamp (pad cols get invn=0)
            float4 wv = *(const float4*)&w[(ph * KH + k) * Cdim + cw];
            float4 iv = *(const float4*)&g_invn[c];
            sNw4[f] = make_float4(wv.x * iv.x, wv.y * iv.y, wv.z * iv.z, wv.w * iv.w);
        }
        // ---- stage duplicated ne / gr ----
#pragma unroll
        for (int i = 0; i < 8; i++) {
            int f = tid + i * 256;            // 2048 float4: 64 k x 32 (row = 64 f2 = 32 f4)
            int k = f >> 5;
            int off = f & 31;
            int src = (ph * KH + k) * (Bdim / 2) + (bBase >> 1) + off;
            sNe4[f] = gNe4[src];
            sGr4[f] = gGr4[src];
        }
        __syncthreads();

        const ulonglong2* neV = (const ulonglong2*)sNe2;  // 32 u2 per k-row
        const ulonglong2* grV = (const ulonglong2*)sGr2;
#pragma unroll 4
        for (int k = 0; k < KH; k++) {
            ulonglong2 neA = neV[k * 32 + ty * 2];
            ulonglong2 neB = neV[k * 32 + ty * 2 + 1];
            ulonglong2 grA = grV[k * 32 + ty * 2];
            ulonglong2 grB = grV[k * 32 + ty * 2 + 1];
            const ulonglong2* nwr = (const ulonglong2*)&sNw[k * CT];
            ulonglong2 nwA = nwr[tx];
            ulonglong2 nwB = nwr[16 + tx];
            unsigned long long nwp[4] = {nwA.x, nwA.y, nwB.x, nwB.y};
            unsigned long long nep[4] = {neA.x, neA.y, neB.x, neB.y};
            unsigned long long grp[4] = {grA.x, grA.y, grB.x, grB.y};
#pragma unroll
            for (int i = 0; i < 4; i++) {
#pragma unroll
                for (int j = 0; j < 4; j++) {
                    ffma2(accC[i][j], nep[i], nwp[j]);
                    ffma2(accG[i][j], grp[i], nwp[j]);
                }
            }
        }
    }

    // ---- epilogue: penalties + exp logits + row-sum atomics ----
    float* out_logit = out;
    float* out_pen = out + (size_t)Bdim * Cdim;

#pragma unroll
    for (int i = 0; i < 4; i++) {
        int b = bBase + ty * 4 + i;
        float sb = g_s[b];
        int lb = labels[b];
        float esum = 0.f;
#pragma unroll
        for (int h = 0; h < 2; h++) {
            int c0 = cBase + h * 64 + tx * 4;
            float2 cA = unpack2(accC[i][h * 2 + 0]);
            float2 cB = unpack2(accC[i][h * 2 + 1]);
            float2 gA = unpack2(accG[i][h * 2 + 0]);
            float2 gB = unpack2(accG[i][h * 2 + 1]);
            float cosv[4] = {cA.x, cA.y, cB.x, cB.y};
            float Gv[4]   = {gA.x, gA.y, gB.x, gB.y};
            if (c0 < Cdim) {  // Cdim % 4 == 0, c0 % 4 == 0 -> whole vec valid
                float pen[4], ev[4];
#pragma unroll
                for (int j = 0; j < 4; j++) {
                    float denom = fmaxf(2.f - 2.f * Gv[j], EPS_F);
                    float win = (sb - cosv[j]) * rsqrtf(denom);
                    if (c0 + j == lb) win = 0.f;  // dw==0 exactly in reference
                    pen[j] = MARGIN_F - fminf(MARGIN_F, win);
                    ev[j] = __expf(SCALE_F * cosv[j] - SCALE_F);
                    esum += ev[j];
                }
                *(float4*)&out_pen[(size_t)b * Cdim + c0] =
                    make_float4(pen[0], pen[1], pen[2], pen[3]);
                *(float4*)&out_logit[(size_t)b * Cdim + c0] =
                    make_float4(ev[0], ev[1], ev[2], ev[3]);
            }
        }
        // reduce esum across the 16 tx lanes
#pragma unroll
        for (int o = 8; o > 0; o >>= 1)
            esum += __shfl_xor_sync(0xffffffffu, esum, o);
        if (tx == 0) atomicAdd(&g_rowsum[b], esum);
    }
}

// ---------------- K4: scale logits by 1/rowsum (MLP 8) ----------------
__global__ __launch_bounds__(256) void k_scale(float* __restrict__ out) {
    int b = blockIdx.x;
    int t = threadIdx.x;
    float inv = 1.f / g_rowsum[b];
    float4* p = (float4*)(out + (size_t)b * Cdim);   // 2000 float4 per row
    float4 v[8];
#pragma unroll
    for (int i = 0; i < 8; i++) {
        int idx = t + i * 256;
        if (idx < Cdim / 4) v[i] = p[idx];
    }
#pragma unroll
    for (int i = 0; i < 8; i++) {
        int idx = t + i * 256;
        if (idx < Cdim / 4) {
            v[i].x *= inv; v[i].y *= inv; v[i].z *= inv; v[i].w *= inv;
            p[idx] = v[i];
        }
    }
}

// ---------------- launch ----------------
extern "C" void kernel_launch(void* const* d_in, const int* in_sizes, int n_in,
                              void* d_out, int out_size) {
    const float* embds = (const float*)d_in[0];   // [256,128]
    const float* w     = (const float*)d_in[1];   // [128,8000]
    const int* labels  = (const int*)d_in[2];     // [256]
    float* out = (float*)d_out;                   // logits[256*8000] then penalties[256*8000]

    static const int kMainSmem = (KH * CT + 4 * KH * BT) * (int)sizeof(float); // 96KB
    cudaFuncSetAttribute(k_main, cudaFuncAttributeMaxDynamicSharedMemorySize, kMainSmem);

    k_rnorm<<<(CPAD + 255) / 256, 256>>>(w);
    k_prep<<<Bdim, Ddim>>>(embds, w, labels);

    dim3 g3(CPAD / CT, Bdim / BT);  // (63, 4)
    k_main<<<g3, 256, kMainSmem>>>(out, w, labels);

    k_scale<<<Bdim, 256>>>(out);
}

// round 5
// speedup vs baseline: 1.4398x; 1.4398x over previous
#include <cuda_runtime.h>
#include <cuda_bf16.h>
#include <cstdint>

#define Bdim 256
#define Ddim 128
#define Cdim 8000
#define CPAD 8064
#define SCALE_F 64.0f
#define MARGIN_F 0.5f
#define EPS_F 1e-12f

// ---------------- device scratch (no allocations allowed) ----------------
// bf16 split tiles, [row][k] with k contiguous, viewed as 16B units (8 bf16).
__device__ uint4 g_nwHi4[CPAD * 16];   // row = c
__device__ uint4 g_nwLo4[CPAD * 16];
__device__ uint4 g_neHi4[Bdim * 16];   // row = b
__device__ uint4 g_neLo4[Bdim * 16];
__device__ uint4 g_grHi4[Bdim * 16];
__device__ uint4 g_grLo4[Bdim * 16];
__device__ float g_invn[CPAD];
__device__ float g_s[Bdim];
__device__ float g_rowsum[Bdim];

// ---------------- warp-MMA helpers (family-safe: ldmatrix + mma.sync) -------
__device__ __forceinline__ uint32_t smem_u32(const void* p) {
    uint32_t a;
    asm("{ .reg .u64 t; cvta.to.shared.u64 t, %1; cvt.u32.u64 %0, t; }"
        : "=r"(a) : "l"(p));
    return a;
}
__device__ __forceinline__ void ldsm_x4(uint32_t& r0, uint32_t& r1,
                                        uint32_t& r2, uint32_t& r3,
                                        uint32_t addr) {
    asm volatile(
        "ldmatrix.sync.aligned.m8n8.x4.shared.b16 {%0,%1,%2,%3}, [%4];"
        : "=r"(r0), "=r"(r1), "=r"(r2), "=r"(r3) : "r"(addr));
}
__device__ __forceinline__ void mma16816(float* d, const uint32_t* a,
                                         const uint32_t* b) {
    asm volatile(
        "mma.sync.aligned.m16n8k16.row.col.f32.bf16.bf16.f32 "
        "{%0,%1,%2,%3}, {%4,%5,%6,%7}, {%8,%9}, {%0,%1,%2,%3};"
        : "+f"(d[0]), "+f"(d[1]), "+f"(d[2]), "+f"(d[3])
        : "r"(a[0]), "r"(a[1]), "r"(a[2]), "r"(a[3]), "r"(b[0]), "r"(b[1]));
}

// smem tile geometry: 128 rows x 136 bf16 (272B rows -> 4-bank shift per row)
#define ROW_U4 17
#define TILE_U4 (128 * ROW_U4)           // 2176 uint4 = 34816 B

// ---------------- K1: invn + bf16-split normalized w, [c][k] ----------------
__global__ __launch_bounds__(256) void k_wsplit(const float* __restrict__ w) {
    extern __shared__ float tile[];      // [k][c] raw w, 128x128 f32 (64KB)
    __shared__ float sinv[128];
    int t = threadIdx.x;
    int cBase = blockIdx.x * 128;
    int u = t & 31;
    int kb = t >> 5;
    bool edge = (cBase + 128 > Cdim);
#pragma unroll 4
    for (int i = 0; i < 16; i++) {
        int k = kb * 16 + i;
        int c = cBase + u * 4;
        float4 v;
        if (!edge) {
            v = *(const float4*)&w[k * Cdim + c];
        } else {
            v.x = (c + 0 < Cdim) ? w[k * Cdim + c + 0] : 0.f;
            v.y = (c + 1 < Cdim) ? w[k * Cdim + c + 1] : 0.f;
            v.z = (c + 2 < Cdim) ? w[k * Cdim + c + 2] : 0.f;
            v.w = (c + 3 < Cdim) ? w[k * Cdim + c + 3] : 0.f;
        }
        *(float4*)&tile[k * 128 + u * 4] = v;
    }
    __syncthreads();
    if (t < 128) {
        float ss = 0.f;
#pragma unroll 8
        for (int k = 0; k < 128; k++) {
            float v = tile[k * 128 + t];
            ss = fmaf(v, v, ss);
        }
        float r = rsqrtf(fmaxf(ss, EPS_F));
        r = (cBase + t < Cdim) ? r : 0.f;
        sinv[t] = r;
        g_invn[cBase + t] = r;
    }
    __syncthreads();
    int c = t & 127;
    int half = t >> 7;
    float inv = sinv[c];
    unsigned* pHi = (unsigned*)g_nwHi4;
    unsigned* pLo = (unsigned*)g_nwLo4;
    int base = (cBase + c) * 64 + half * 32;
#pragma unroll 4
    for (int i = 0; i < 32; i++) {
        int k = half * 64 + i * 2;
        float v0 = tile[k * 128 + c] * inv;
        float v1 = tile[(k + 1) * 128 + c] * inv;
        __nv_bfloat16 h0 = __float2bfloat16(v0);
        __nv_bfloat16 h1 = __float2bfloat16(v1);
        __nv_bfloat16 l0 = __float2bfloat16(v0 - __bfloat162float(h0));
        __nv_bfloat16 l1 = __float2bfloat16(v1 - __bfloat162float(h1));
        pHi[base + i] = (unsigned)__bfloat16_as_ushort(h0) |
                        ((unsigned)__bfloat16_as_ushort(h1) << 16);
        pLo[base + i] = (unsigned)__bfloat16_as_ushort(l0) |
                        ((unsigned)__bfloat16_as_ushort(l1) << 16);
    }
}

// ---------------- K2: normalize embds, gather gr, splits, s[b] --------------
__global__ void k_prep(const float* __restrict__ embds,
                       const float* __restrict__ w,
                       const int* __restrict__ labels) {
    int b = blockIdx.x;
    int d = threadIdx.x;  // 128 threads
    __shared__ float redA[4];
    __shared__ float redB[4];

    float e = embds[b * Ddim + d];
    float v = e * e;
#pragma unroll
    for (int o = 16; o > 0; o >>= 1) v += __shfl_xor_sync(0xffffffffu, v, o);
    if ((d & 31) == 0) redA[d >> 5] = v;
    __syncthreads();
    float ss = redA[0] + redA[1] + redA[2] + redA[3];
    float ne = e * rsqrtf(fmaxf(ss, EPS_F));

    int lb = labels[b];
    float gr = w[d * Cdim + lb] * g_invn[lb];

    __nv_bfloat16 neh = __float2bfloat16(ne);
    __nv_bfloat16 nel = __float2bfloat16(ne - __bfloat162float(neh));
    __nv_bfloat16 grh = __float2bfloat16(gr);
    __nv_bfloat16 grl = __float2bfloat16(gr - __bfloat162float(grh));
    ((unsigned short*)g_neHi4)[b * 128 + d] = __bfloat16_as_ushort(neh);
    ((unsigned short*)g_neLo4)[b * 128 + d] = __bfloat16_as_ushort(nel);
    ((unsigned short*)g_grHi4)[b * 128 + d] = __bfloat16_as_ushort(grh);
    ((unsigned short*)g_grLo4)[b * 128 + d] = __bfloat16_as_ushort(grl);

    float sv = ne * gr;
#pragma unroll
    for (int o = 16; o > 0; o >>= 1) sv += __shfl_xor_sync(0xffffffffu, sv, o);
    if ((d & 31) == 0) redB[d >> 5] = sv;
    __syncthreads();
    if (d == 0) {
        g_s[b] = redB[0] + redB[1] + redB[2] + redB[3];
        g_rowsum[b] = 0.f;
    }
}

// ---------------- K3: warp-MMA dual GEMM + epilogue ----------------
// smem: 6 padded bf16 tiles (neHi, neLo, grHi, grLo, nwHi, nwLo) = 204KB
__global__ __launch_bounds__(256, 1) void k_main(float* __restrict__ out,
                                                 const int* __restrict__ labels) {
    extern __shared__ uint4 smem4[];
    const int tid = threadIdx.x;
    const int wid = tid >> 5;
    const int lane = tid & 31;
    const int cBase = blockIdx.x * 128;
    const int bBase = blockIdx.y * 128;

    // ---- stage 6 tiles into padded smem ----
    {
        const uint4* srcs[6] = {g_neHi4 + bBase * 16, g_neLo4 + bBase * 16,
                                g_grHi4 + bBase * 16, g_grLo4 + bBase * 16,
                                g_nwHi4 + cBase * 16, g_nwLo4 + cBase * 16};
#pragma unroll
        for (int t6 = 0; t6 < 6; t6++) {
            const uint4* src = srcs[t6];
            uint4* dst = smem4 + t6 * TILE_U4;
#pragma unroll
            for (int i = 0; i < 8; i++) {
                int idx = tid + i * 256;
                dst[(idx >> 4) * ROW_U4 + (idx & 15)] = src[idx];
            }
        }
    }
    __syncthreads();

    const uint32_t sb0 = smem_u32(smem4);
    const int m0 = (wid >> 1) * 32;          // warp m-range (b)
    const int n0 = (wid & 1) * 64;           // warp n-range (c)
    const int rowA = (lane & 7) + ((lane >> 3) & 1) * 8;
    const int uA = lane >> 4;
    const int rowB = (lane & 7) + (lane >> 4) * 8;
    const int uB = (lane >> 3) & 1;

    float accC[2][8][4];
    float accG[2][8][4];
#pragma unroll
    for (int mt = 0; mt < 2; mt++)
#pragma unroll
        for (int j = 0; j < 8; j++)
#pragma unroll
            for (int r = 0; r < 4; r++) { accC[mt][j][r] = 0.f; accG[mt][j][r] = 0.f; }

    // passes: hi*hi, lo*hi, hi*lo  (lo*lo term negligible: < 2^-18 relative)
    const int pa[3] = {0, 1, 0};   // ne/gr tile select (0=Hi, 1=Lo)
    const int pb[3] = {4, 4, 5};   // nw tile select    (4=Hi, 5=Lo)
#pragma unroll
    for (int p = 0; p < 3; p++) {
        uint32_t baseNe = sb0 + (uint32_t)(pa[p] * TILE_U4 * 16);
        uint32_t baseGr = sb0 + (uint32_t)((pa[p] + 2) * TILE_U4 * 16);
        uint32_t baseB  = sb0 + (uint32_t)(pb[p] * TILE_U4 * 16);
#pragma unroll 2
        for (int ks = 0; ks < 8; ks++) {
            uint32_t bf[8][2];
#pragma unroll
            for (int jp = 0; jp < 4; jp++) {
                uint32_t addr = baseB +
                    (uint32_t)(((n0 + jp * 16 + rowB) * ROW_U4 + ks * 2 + uB) * 16);
                ldsm_x4(bf[2 * jp][0], bf[2 * jp][1],
                        bf[2 * jp + 1][0], bf[2 * jp + 1][1], addr);
            }
            uint32_t an[2][4], ag[2][4];
#pragma unroll
            for (int mt = 0; mt < 2; mt++) {
                uint32_t aoff =
                    (uint32_t)(((m0 + mt * 16 + rowA) * ROW_U4 + ks * 2 + uA) * 16);
                ldsm_x4(an[mt][0], an[mt][1], an[mt][2], an[mt][3], baseNe + aoff);
                ldsm_x4(ag[mt][0], ag[mt][1], ag[mt][2], ag[mt][3], baseGr + aoff);
            }
#pragma unroll
            for (int mt = 0; mt < 2; mt++)
#pragma unroll
                for (int j = 0; j < 8; j++) {
                    mma16816(accC[mt][j], an[mt], bf[j]);
                    mma16816(accG[mt][j], ag[mt], bf[j]);
                }
        }
    }

    // ---- epilogue: fragments are register-resident ----
    float* out_logit = out;
    float* out_pen = out + (size_t)Bdim * Cdim;
#pragma unroll
    for (int mt = 0; mt < 2; mt++) {
#pragma unroll
        for (int h = 0; h < 2; h++) {
            int b = bBase + m0 + mt * 16 + h * 8 + (lane >> 2);
            float sbv = g_s[b];
            int lb = labels[b];
            float esum = 0.f;
#pragma unroll
            for (int j = 0; j < 8; j++) {
                int c0 = cBase + n0 + j * 8 + (lane & 3) * 2;
                if (c0 < Cdim) {   // Cdim even, c0 even -> pair fully valid
                    float cv0 = accC[mt][j][h * 2 + 0];
                    float cv1 = accC[mt][j][h * 2 + 1];
                    float g0 = accG[mt][j][h * 2 + 0];
                    float g1 = accG[mt][j][h * 2 + 1];
                    float w0 = (sbv - cv0) * rsqrtf(fmaxf(2.f - 2.f * g0, EPS_F));
                    float w1 = (sbv - cv1) * rsqrtf(fmaxf(2.f - 2.f * g1, EPS_F));
                    if (c0 == lb) w0 = 0.f;       // dw == 0 exactly in reference
                    if (c0 + 1 == lb) w1 = 0.f;
                    float p0 = MARGIN_F - fminf(MARGIN_F, w0);
                    float p1 = MARGIN_F - fminf(MARGIN_F, w1);
                    float e0 = __expf(SCALE_F * cv0 - SCALE_F);
                    float e1 = __expf(SCALE_F * cv1 - SCALE_F);
                    esum += e0 + e1;
                    *(float2*)&out_pen[(size_t)b * Cdim + c0] = make_float2(p0, p1);
                    *(float2*)&out_logit[(size_t)b * Cdim + c0] = make_float2(e0, e1);
                }
            }
            esum += __shfl_xor_sync(0xffffffffu, esum, 1);
            esum += __shfl_xor_sync(0xffffffffu, esum, 2);
            if ((lane & 3) == 0) atomicAdd(&g_rowsum[b], esum);
        }
    }
}

// ---------------- K4: scale logits by 1/rowsum ----------------
__global__ __launch_bounds__(512) void k_scale(float* __restrict__ out) {
    __shared__ float sInv;
    int b = blockIdx.x;
    int t = threadIdx.x;
    if (t == 0) sInv = 1.f / g_rowsum[b];
    __syncthreads();
    float inv = sInv;
    float4* p = (float4*)(out + (size_t)b * Cdim);
#pragma unroll
    for (int i = 0; i < 4; i++) {
        int idx = t + i * 512;
        if (idx < Cdim / 4) {
            float4 v = p[idx];
            v.x *= inv; v.y *= inv; v.z *= inv; v.w *= inv;
            p[idx] = v;
        }
    }
}

// ---------------- launch ----------------
extern "C" void kernel_launch(void* const* d_in, const int* in_sizes, int n_in,
                              void* d_out, int out_size) {
    const float* embds = (const float*)d_in[0];   // [256,128]
    const float* w     = (const float*)d_in[1];   // [128,8000]
    const int* labels  = (const int*)d_in[2];     // [256]
    float* out = (float*)d_out;                   // logits then penalties

    const int kWsplitSmem = 128 * 128 * (int)sizeof(float);     // 64KB
    const int kMainSmem = 6 * TILE_U4 * 16;                     // 208896 B
    cudaFuncSetAttribute(k_wsplit, cudaFuncAttributeMaxDynamicSharedMemorySize,
                         kWsplitSmem);
    cudaFuncSetAttribute(k_main, cudaFuncAttributeMaxDynamicSharedMemorySize,
                         kMainSmem);

    k_wsplit<<<CPAD / 128, 256, kWsplitSmem>>>(w);   // 63 blocks
    k_prep<<<Bdim, Ddim>>>(embds, w, labels);

    dim3 g3(CPAD / 128, 2);                          // (63, 2)
    k_main<<<g3, 256, kMainSmem>>>(out, labels);

    k_scale<<<Bdim, 512>>>(out);
}

// round 6
// speedup vs baseline: 1.4412x; 1.0010x over previous
#include <cuda_runtime.h>
#include <cuda_bf16.h>
#include <cstdint>

#define Bdim 256
#define Ddim 128
#define Cdim 8000
#define CPAD 8064
#define SCALE_F 64.0f
#define MARGIN_F 0.5f
#define EPS_F 1e-12f
#define NCTA 126   // k_main grid size (63 x 2), all resident (1 CTA/SM, 148 SMs)

// ---------------- device scratch (no allocations allowed) ----------------
__device__ uint4 g_nwHi4[CPAD * 16];   // row = c, 16 x 16B of bf16 along k
__device__ uint4 g_nwLo4[CPAD * 16];
__device__ uint4 g_neHi4[Bdim * 16];   // row = b
__device__ uint4 g_neLo4[Bdim * 16];
__device__ uint4 g_grHi4[Bdim * 16];
__device__ uint4 g_grLo4[Bdim * 16];
__device__ float g_invn[CPAD];
__device__ float g_s[Bdim];
__device__ float g_rowsum[Bdim];
__device__ int g_count;

// ---------------- warp-MMA helpers (family-safe: ldmatrix + mma.sync) -------
__device__ __forceinline__ uint32_t smem_u32(const void* p) {
    uint32_t a;
    asm("{ .reg .u64 t; cvta.to.shared.u64 t, %1; cvt.u32.u64 %0, t; }"
        : "=r"(a) : "l"(p));
    return a;
}
__device__ __forceinline__ void ldsm_x4(uint32_t& r0, uint32_t& r1,
                                        uint32_t& r2, uint32_t& r3,
                                        uint32_t addr) {
    asm volatile(
        "ldmatrix.sync.aligned.m8n8.x4.shared.b16 {%0,%1,%2,%3}, [%4];"
        : "=r"(r0), "=r"(r1), "=r"(r2), "=r"(r3) : "r"(addr));
}
__device__ __forceinline__ void mma16816(float* d, const uint32_t* a,
                                         const uint32_t* b) {
    asm volatile(
        "mma.sync.aligned.m16n8k16.row.col.f32.bf16.bf16.f32 "
        "{%0,%1,%2,%3}, {%4,%5,%6,%7}, {%8,%9}, {%0,%1,%2,%3};"
        : "+f"(d[0]), "+f"(d[1]), "+f"(d[2]), "+f"(d[3])
        : "r"(a[0]), "r"(a[1]), "r"(a[2]), "r"(a[3]), "r"(b[0]), "r"(b[1]));
}

// smem tile geometry (k_main): 128 rows x 136 bf16 (272B rows -> 4-bank shift)
#define ROW_U4 17
#define TILE_U4 (128 * ROW_U4)           // 2176 uint4 = 34816 B

// ---------------- K1: invn + bf16-split normalized w, [c][k] ----------------
// smem tile padded to 132 floats/row: float4-aligned stores, conflict-free
// column reads (bank = (4k + c) % 32, c consecutive across lanes).
#define WPAD 132
__global__ __launch_bounds__(256) void k_wsplit(const float* __restrict__ w) {
    extern __shared__ float tile[];      // [k][c] raw w, 128 x WPAD
    __shared__ float red2[256];
    __shared__ float sinv[128];
    int t = threadIdx.x;
    int cBase = blockIdx.x * 128;
    int u = t & 31;
    int kb = t >> 5;
    bool edge = (cBase + 128 > Cdim);
#pragma unroll 4
    for (int i = 0; i < 16; i++) {
        int k = kb * 16 + i;
        int c = cBase + u * 4;
        float4 v;
        if (!edge) {
            v = *(const float4*)&w[k * Cdim + c];
        } else {
            v.x = (c + 0 < Cdim) ? w[k * Cdim + c + 0] : 0.f;
            v.y = (c + 1 < Cdim) ? w[k * Cdim + c + 1] : 0.f;
            v.z = (c + 2 < Cdim) ? w[k * Cdim + c + 2] : 0.f;
            v.w = (c + 3 < Cdim) ? w[k * Cdim + c + 3] : 0.f;
        }
        *(float4*)&tile[k * WPAD + u * 4] = v;
    }
    __syncthreads();
    // column sums of squares, split across 2 k-halves
    {
        int c = t & 127;
        int kh = t >> 7;
        float ss = 0.f;
#pragma unroll 8
        for (int k = kh * 64; k < kh * 64 + 64; k++) {
            float v = tile[k * WPAD + c];
            ss = fmaf(v, v, ss);
        }
        red2[t] = ss;
    }
    __syncthreads();
    if (t < 128) {
        float r = rsqrtf(fmaxf(red2[t] + red2[t + 128], EPS_F));
        r = (cBase + t < Cdim) ? r : 0.f;
        sinv[t] = r;
        g_invn[cBase + t] = r;
    }
    __syncthreads();
    // split + coalesced uint4 stores: thread owns (c, k-half)
    {
        int c = t & 127;
        int kh = t >> 7;
        float inv = sinv[c];
#pragma unroll
        for (int q = 0; q < 8; q++) {
            int kq = kh * 8 + q;           // 16B unit (8 bf16 = 8 k) index
            uint32_t hi[4], lo[4];
#pragma unroll
            for (int uu = 0; uu < 4; uu++) {
                float v0 = tile[(kq * 8 + uu * 2 + 0) * WPAD + c] * inv;
                float v1 = tile[(kq * 8 + uu * 2 + 1) * WPAD + c] * inv;
                __nv_bfloat16 h0 = __float2bfloat16(v0);
                __nv_bfloat16 h1 = __float2bfloat16(v1);
                __nv_bfloat16 l0 = __float2bfloat16(v0 - __bfloat162float(h0));
                __nv_bfloat16 l1 = __float2bfloat16(v1 - __bfloat162float(h1));
                hi[uu] = (uint32_t)__bfloat16_as_ushort(h0) |
                         ((uint32_t)__bfloat16_as_ushort(h1) << 16);
                lo[uu] = (uint32_t)__bfloat16_as_ushort(l0) |
                         ((uint32_t)__bfloat16_as_ushort(l1) << 16);
            }
            int idx = (cBase + c) * 16 + kq;
            g_nwHi4[idx] = make_uint4(hi[0], hi[1], hi[2], hi[3]);
            g_nwLo4[idx] = make_uint4(lo[0], lo[1], lo[2], lo[3]);
        }
    }
}

// ---------------- K2: normalize embds, gather gr, splits, s[b] --------------
__global__ void k_prep(const float* __restrict__ embds,
                       const float* __restrict__ w,
                       const int* __restrict__ labels) {
    int b = blockIdx.x;
    int d = threadIdx.x;  // 128 threads
    __shared__ float redA[4];
    __shared__ float redB[4];

    float e = embds[b * Ddim + d];
    float v = e * e;
#pragma unroll
    for (int o = 16; o > 0; o >>= 1) v += __shfl_xor_sync(0xffffffffu, v, o);
    if ((d & 31) == 0) redA[d >> 5] = v;
    __syncthreads();
    float ss = redA[0] + redA[1] + redA[2] + redA[3];
    float ne = e * rsqrtf(fmaxf(ss, EPS_F));

    int lb = labels[b];
    float gr = w[d * Cdim + lb] * g_invn[lb];

    __nv_bfloat16 neh = __float2bfloat16(ne);
    __nv_bfloat16 nel = __float2bfloat16(ne - __bfloat162float(neh));
    __nv_bfloat16 grh = __float2bfloat16(gr);
    __nv_bfloat16 grl = __float2bfloat16(gr - __bfloat162float(grh));
    ((unsigned short*)g_neHi4)[b * 128 + d] = __bfloat16_as_ushort(neh);
    ((unsigned short*)g_neLo4)[b * 128 + d] = __bfloat16_as_ushort(nel);
    ((unsigned short*)g_grHi4)[b * 128 + d] = __bfloat16_as_ushort(grh);
    ((unsigned short*)g_grLo4)[b * 128 + d] = __bfloat16_as_ushort(grl);

    float sv = ne * gr;
#pragma unroll
    for (int o = 16; o > 0; o >>= 1) sv += __shfl_xor_sync(0xffffffffu, sv, o);
    if ((d & 31) == 0) redB[d >> 5] = sv;
    __syncthreads();
    if (d == 0) {
        g_s[b] = redB[0] + redB[1] + redB[2] + redB[3];
        g_rowsum[b] = 0.f;
        if (b == 0) g_count = 0;
    }
}

// ---------------- K3: warp-MMA dual GEMM + fused softmax epilogue ----------
// smem: 6 padded bf16 tiles = 204KB -> 1 CTA/SM; grid 126 <= 148 SMs, so all
// CTAs are co-resident: the global spin barrier below cannot deadlock.
__global__ __launch_bounds__(256, 1) void k_main(float* __restrict__ out,
                                                 const int* __restrict__ labels) {
    extern __shared__ uint4 smem4[];
    const int tid = threadIdx.x;
    const int wid = tid >> 5;
    const int lane = tid & 31;
    const int cBase = blockIdx.x * 128;
    const int bBase = blockIdx.y * 128;

    // ---- stage 6 tiles into padded smem ----
    {
        const uint4* srcs[6] = {g_neHi4 + bBase * 16, g_neLo4 + bBase * 16,
                                g_grHi4 + bBase * 16, g_grLo4 + bBase * 16,
                                g_nwHi4 + cBase * 16, g_nwLo4 + cBase * 16};
#pragma unroll
        for (int t6 = 0; t6 < 6; t6++) {
            const uint4* src = srcs[t6];
            uint4* dst = smem4 + t6 * TILE_U4;
#pragma unroll
            for (int i = 0; i < 8; i++) {
                int idx = tid + i * 256;
                dst[(idx >> 4) * ROW_U4 + (idx & 15)] = src[idx];
            }
        }
    }
    __syncthreads();

    const uint32_t sb0 = smem_u32(smem4);
    const int m0 = (wid >> 1) * 32;          // warp m-range (b)
    const int n0 = (wid & 1) * 64;           // warp n-range (c)
    const int rowA = (lane & 7) + ((lane >> 3) & 1) * 8;
    const int uA = lane >> 4;
    const int rowB = (lane & 7) + (lane >> 4) * 8;
    const int uB = (lane >> 3) & 1;

    float accC[2][8][4];
    float accG[2][8][4];
#pragma unroll
    for (int mt = 0; mt < 2; mt++)
#pragma unroll
        for (int j = 0; j < 8; j++)
#pragma unroll
            for (int r = 0; r < 4; r++) { accC[mt][j][r] = 0.f; accG[mt][j][r] = 0.f; }

    // passes: hi*hi, lo*hi, hi*lo  (lo*lo term negligible: < 2^-18 relative)
    const int pa[3] = {0, 1, 0};   // ne/gr tile select (0=Hi, 1=Lo)
    const int pb[3] = {4, 4, 5};   // nw tile select    (4=Hi, 5=Lo)
#pragma unroll
    for (int p = 0; p < 3; p++) {
        uint32_t baseNe = sb0 + (uint32_t)(pa[p] * TILE_U4 * 16);
        uint32_t baseGr = sb0 + (uint32_t)((pa[p] + 2) * TILE_U4 * 16);
        uint32_t baseB  = sb0 + (uint32_t)(pb[p] * TILE_U4 * 16);
#pragma unroll 2
        for (int ks = 0; ks < 8; ks++) {
            uint32_t bf[8][2];
#pragma unroll
            for (int jp = 0; jp < 4; jp++) {
                uint32_t addr = baseB +
                    (uint32_t)(((n0 + jp * 16 + rowB) * ROW_U4 + ks * 2 + uB) * 16);
                ldsm_x4(bf[2 * jp][0], bf[2 * jp][1],
                        bf[2 * jp + 1][0], bf[2 * jp + 1][1], addr);
            }
            uint32_t an[2][4], ag[2][4];
#pragma unroll
            for (int mt = 0; mt < 2; mt++) {
                uint32_t aoff =
                    (uint32_t)(((m0 + mt * 16 + rowA) * ROW_U4 + ks * 2 + uA) * 16);
                ldsm_x4(an[mt][0], an[mt][1], an[mt][2], an[mt][3], baseNe + aoff);
                ldsm_x4(ag[mt][0], ag[mt][1], ag[mt][2], ag[mt][3], baseGr + aoff);
            }
#pragma unroll
            for (int mt = 0; mt < 2; mt++)
#pragma unroll
                for (int j = 0; j < 8; j++) {
                    mma16816(accC[mt][j], an[mt], bf[j]);
                    mma16816(accG[mt][j], ag[mt], bf[j]);
                }
        }
    }

    // ---- epilogue part 1: penalties + exp (kept in accC) + rowsum atomics --
    float* out_logit = out;
    float* out_pen = out + (size_t)Bdim * Cdim;
#pragma unroll
    for (int mt = 0; mt < 2; mt++) {
#pragma unroll
        for (int h = 0; h < 2; h++) {
            int b = bBase + m0 + mt * 16 + h * 8 + (lane >> 2);
            float sbv = g_s[b];
            int lb = labels[b];
            float esum = 0.f;
#pragma unroll
            for (int j = 0; j < 8; j++) {
                int c0 = cBase + n0 + j * 8 + (lane & 3) * 2;
                if (c0 < Cdim) {   // Cdim even, c0 even -> pair fully valid
                    float cv0 = accC[mt][j][h * 2 + 0];
                    float cv1 = accC[mt][j][h * 2 + 1];
                    float g0 = accG[mt][j][h * 2 + 0];
                    float g1 = accG[mt][j][h * 2 + 1];
                    float w0 = (sbv - cv0) * rsqrtf(fmaxf(2.f - 2.f * g0, EPS_F));
                    float w1 = (sbv - cv1) * rsqrtf(fmaxf(2.f - 2.f * g1, EPS_F));
                    if (c0 == lb) w0 = 0.f;       // dw == 0 exactly in reference
                    if (c0 + 1 == lb) w1 = 0.f;
                    float p0 = MARGIN_F - fminf(MARGIN_F, w0);
                    float p1 = MARGIN_F - fminf(MARGIN_F, w1);
                    float e0 = __expf(SCALE_F * cv0 - SCALE_F);
                    float e1 = __expf(SCALE_F * cv1 - SCALE_F);
                    accC[mt][j][h * 2 + 0] = e0;   // stash ev in registers
                    accC[mt][j][h * 2 + 1] = e1;
                    esum += e0 + e1;
                    *(float2*)&out_pen[(size_t)b * Cdim + c0] = make_float2(p0, p1);
                }
            }
            esum += __shfl_xor_sync(0xffffffffu, esum, 1);
            esum += __shfl_xor_sync(0xffffffffu, esum, 2);
            if ((lane & 3) == 0) atomicAdd(&g_rowsum[b], esum);
        }
    }

    // ---- grid-wide barrier (all 126 CTAs resident) ----
    __threadfence();
    __syncthreads();
    if (tid == 0) {
        atomicAdd(&g_count, 1);
        while (*(volatile int*)&g_count < NCTA) { }
    }
    __syncthreads();

    // ---- epilogue part 2: scaled logits ----
#pragma unroll
    for (int mt = 0; mt < 2; mt++) {
#pragma unroll
        for (int h = 0; h < 2; h++) {
            int b = bBase + m0 + mt * 16 + h * 8 + (lane >> 2);
            float inv = 1.f / __ldcg(&g_rowsum[b]);
#pragma unroll
            for (int j = 0; j < 8; j++) {
                int c0 = cBase + n0 + j * 8 + (lane & 3) * 2;
                if (c0 < Cdim) {
                    float e0 = accC[mt][j][h * 2 + 0] * inv;
                    float e1 = accC[mt][j][h * 2 + 1] * inv;
                    *(float2*)&out_logit[(size_t)b * Cdim + c0] =
                        make_float2(e0, e1);
                }
            }
        }
    }
}

// ---------------- launch ----------------
extern "C" void kernel_launch(void* const* d_in, const int* in_sizes, int n_in,
                              void* d_out, int out_size) {
    const float* embds = (const float*)d_in[0];   // [256,128]
    const float* w     = (const float*)d_in[1];   // [128,8000]
    const int* labels  = (const int*)d_in[2];     // [256]
    float* out = (float*)d_out;                   // logits then penalties

    const int kWsplitSmem = 128 * WPAD * (int)sizeof(float);    // 67584 B
    const int kMainSmem = 6 * TILE_U4 * 16;                     // 208896 B
    cudaFuncSetAttribute(k_wsplit, cudaFuncAttributeMaxDynamicSharedMemorySize,
                         kWsplitSmem);
    cudaFuncSetAttribute(k_main, cudaFuncAttributeMaxDynamicSharedMemorySize,
                         kMainSmem);

    k_wsplit<<<CPAD / 128, 256, kWsplitSmem>>>(w);   // 63 blocks
    k_prep<<<Bdim, Ddim>>>(embds, w, labels);

    dim3 g3(CPAD / 128, 2);                          // (63, 2) = 126 CTAs
    k_main<<<g3, 256, kMainSmem>>>(out, labels);
}

// round 7
// speedup vs baseline: 1.6422x; 1.1394x over previous
#include <cuda_runtime.h>
#include <cuda_bf16.h>
#include <cstdint>

#define Bdim 256
#define Ddim 128
#define Cdim 8000
#define CPAD 8064
#define SCALE_F 64.0f
#define MARGIN_F 0.5f
#define EPS_F 1e-12f
#define NCTA 126   // k_main grid (63 x 2); 1 CTA/SM, 148 SMs -> all co-resident

// ---------------- device scratch (no allocations allowed) ----------------
__device__ uint4 g_neHi4[Bdim * 16];   // row = b, 16 x 16B of bf16 along k
__device__ uint4 g_neLo4[Bdim * 16];
__device__ uint4 g_grHi4[Bdim * 16];
__device__ uint4 g_grLo4[Bdim * 16];
__device__ float g_s[Bdim];
__device__ float g_rowsum[Bdim];
__device__ int g_count;

// ---------------- warp-MMA helpers (family-safe: ldmatrix + mma.sync) -------
__device__ __forceinline__ uint32_t smem_u32(const void* p) {
    uint32_t a;
    asm("{ .reg .u64 t; cvta.to.shared.u64 t, %1; cvt.u32.u64 %0, t; }"
        : "=r"(a) : "l"(p));
    return a;
}
__device__ __forceinline__ void ldsm_x4(uint32_t& r0, uint32_t& r1,
                                        uint32_t& r2, uint32_t& r3,
                                        uint32_t addr) {
    asm volatile(
        "ldmatrix.sync.aligned.m8n8.x4.shared.b16 {%0,%1,%2,%3}, [%4];"
        : "=r"(r0), "=r"(r1), "=r"(r2), "=r"(r3) : "r"(addr));
}
__device__ __forceinline__ void mma16816(float* d, const uint32_t* a,
                                         const uint32_t* b) {
    asm volatile(
        "mma.sync.aligned.m16n8k16.row.col.f32.bf16.bf16.f32 "
        "{%0,%1,%2,%3}, {%4,%5,%6,%7}, {%8,%9}, {%0,%1,%2,%3};"
        : "+f"(d[0]), "+f"(d[1]), "+f"(d[2]), "+f"(d[3])
        : "r"(a[0]), "r"(a[1]), "r"(a[2]), "r"(a[3]), "r"(b[0]), "r"(b[1]));
}

// smem tile geometry: 128 rows x 136 bf16 (272B rows -> 4-bank shift per row)
#define ROW_U4 17
#define TILE_U4 (128 * ROW_U4)           // 2176 uint4 = 34816 B
// layout: [0..4) ne/gr hi/lo tiles; [4..6) nw hi/lo tiles.
// The nw region (69632 B) doubles as the raw fp32 w staging area (65536 B).

// ---------------- K2: normalize embds, gather+normalize gr, splits, s[b] ----
__global__ void k_prep(const float* __restrict__ embds,
                       const float* __restrict__ w,
                       const int* __restrict__ labels) {
    int b = blockIdx.x;
    int d = threadIdx.x;  // 128 threads
    __shared__ float redA[4];
    __shared__ float redC[4];
    __shared__ float redB[4];

    float e = embds[b * Ddim + d];
    int lb = labels[b];
    float wv = w[d * Cdim + lb];

    float v = e * e;
    float ww = wv * wv;
#pragma unroll
    for (int o = 16; o > 0; o >>= 1) {
        v += __shfl_xor_sync(0xffffffffu, v, o);
        ww += __shfl_xor_sync(0xffffffffu, ww, o);
    }
    if ((d & 31) == 0) { redA[d >> 5] = v; redC[d >> 5] = ww; }
    __syncthreads();
    float ss = redA[0] + redA[1] + redA[2] + redA[3];
    float ss2 = redC[0] + redC[1] + redC[2] + redC[3];
    float ne = e * rsqrtf(fmaxf(ss, EPS_F));
    float gr = wv * rsqrtf(fmaxf(ss2, EPS_F));

    __nv_bfloat16 neh = __float2bfloat16(ne);
    __nv_bfloat16 nel = __float2bfloat16(ne - __bfloat162float(neh));
    __nv_bfloat16 grh = __float2bfloat16(gr);
    __nv_bfloat16 grl = __float2bfloat16(gr - __bfloat162float(grh));
    ((unsigned short*)g_neHi4)[b * 128 + d] = __bfloat16_as_ushort(neh);
    ((unsigned short*)g_neLo4)[b * 128 + d] = __bfloat16_as_ushort(nel);
    ((unsigned short*)g_grHi4)[b * 128 + d] = __bfloat16_as_ushort(grh);
    ((unsigned short*)g_grLo4)[b * 128 + d] = __bfloat16_as_ushort(grl);

    float sv = ne * gr;
#pragma unroll
    for (int o = 16; o > 0; o >>= 1) sv += __shfl_xor_sync(0xffffffffu, sv, o);
    if ((d & 31) == 0) redB[d >> 5] = sv;
    __syncthreads();
    if (d == 0) {
        g_s[b] = redB[0] + redB[1] + redB[2] + redB[3];
        g_rowsum[b] = 0.f;
        if (b == 0) g_count = 0;
    }
}

// ---------------- K3: fused w-normalize/split + dual GEMM + softmax ---------
// smem: 4 ne/gr tiles + nw hi/lo region (doubles as raw w staging) = 204KB.
__global__ __launch_bounds__(256, 1) void k_main(float* __restrict__ out,
                                                 const float* __restrict__ w,
                                                 const int* __restrict__ labels) {
    extern __shared__ uint4 smem4[];
    __shared__ float red2[256];
    __shared__ float sinv[128];
    const int tid = threadIdx.x;
    const int wid = tid >> 5;
    const int lane = tid & 31;
    const int cBase = blockIdx.x * 128;
    const int bBase = blockIdx.y * 128;

    // ---- stage ne/gr tiles + raw w chunk ----
    {
        const uint4* srcs[4] = {g_neHi4 + bBase * 16, g_neLo4 + bBase * 16,
                                g_grHi4 + bBase * 16, g_grLo4 + bBase * 16};
#pragma unroll
        for (int t4 = 0; t4 < 4; t4++) {
            const uint4* src = srcs[t4];
            uint4* dst = smem4 + t4 * TILE_U4;
#pragma unroll
            for (int i = 0; i < 8; i++) {
                int idx = tid + i * 256;
                dst[(idx >> 4) * ROW_U4 + (idx & 15)] = src[idx];
            }
        }
        // raw w chunk [k][c], plain 128x128 fp32, into the nw region
        float* raw = (float*)(smem4 + 4 * TILE_U4);
        int u = tid & 31;           // c quad
        int kb = tid >> 5;          // k group
        bool edge = (cBase + 128 > Cdim);
#pragma unroll 4
        for (int i = 0; i < 16; i++) {
            int k = kb * 16 + i;
            int c = cBase + u * 4;
            float4 v;
            if (!edge) {
                v = *(const float4*)&w[k * Cdim + c];
            } else {
                v.x = (c + 0 < Cdim) ? w[k * Cdim + c + 0] : 0.f;
                v.y = (c + 1 < Cdim) ? w[k * Cdim + c + 1] : 0.f;
                v.z = (c + 2 < Cdim) ? w[k * Cdim + c + 2] : 0.f;
                v.w = (c + 3 < Cdim) ? w[k * Cdim + c + 3] : 0.f;
            }
            *(float4*)&raw[k * 128 + u * 4] = v;
        }
    }
    __syncthreads();

    // ---- column norms of the raw chunk (conflict-free: bank = c % 32) ----
    {
        const float* raw = (const float*)(smem4 + 4 * TILE_U4);
        int c = tid & 127;
        int kh = tid >> 7;
        float ss = 0.f;
#pragma unroll 8
        for (int k = kh * 64; k < kh * 64 + 64; k++) {
            float v = raw[k * 128 + c];
            ss = fmaf(v, v, ss);
        }
        red2[tid] = ss;
    }
    __syncthreads();
    if (tid < 128) {
        float r = rsqrtf(fmaxf(red2[tid] + red2[tid + 128], EPS_F));
        sinv[tid] = r;
    }
    __syncthreads();

    // ---- in-place convert: raw fp32 -> bf16 hi/lo nw tiles (MMA layout) ----
    {
        const float* raw = (const float*)(smem4 + 4 * TILE_U4);
        int c = tid & 127;
        int kh = tid >> 7;
        float inv = sinv[c];
        uint4 hiu[8], lou[8];
#pragma unroll
        for (int q = 0; q < 8; q++) {
            int kq = kh * 8 + q;
            uint32_t hi[4], lo[4];
#pragma unroll
            for (int uu = 0; uu < 4; uu++) {
                float v0 = raw[(kq * 8 + uu * 2 + 0) * 128 + c] * inv;
                float v1 = raw[(kq * 8 + uu * 2 + 1) * 128 + c] * inv;
                __nv_bfloat16 h0 = __float2bfloat16(v0);
                __nv_bfloat16 h1 = __float2bfloat16(v1);
                __nv_bfloat16 l0 = __float2bfloat16(v0 - __bfloat162float(h0));
                __nv_bfloat16 l1 = __float2bfloat16(v1 - __bfloat162float(h1));
                hi[uu] = (uint32_t)__bfloat16_as_ushort(h0) |
                         ((uint32_t)__bfloat16_as_ushort(h1) << 16);
                lo[uu] = (uint32_t)__bfloat16_as_ushort(l0) |
                         ((uint32_t)__bfloat16_as_ushort(l1) << 16);
            }
            hiu[q] = make_uint4(hi[0], hi[1], hi[2], hi[3]);
            lou[q] = make_uint4(lo[0], lo[1], lo[2], lo[3]);
        }
        __syncthreads();   // all raw reads done before overwriting the region
        uint4* nwHi = smem4 + 4 * TILE_U4;
        uint4* nwLo = smem4 + 5 * TILE_U4;
#pragma unroll
        for (int q = 0; q < 8; q++) {
            int kq = kh * 8 + q;
            nwHi[c * ROW_U4 + kq] = hiu[q];
            nwLo[c * ROW_U4 + kq] = lou[q];
        }
    }
    __syncthreads();

    const uint32_t sb0 = smem_u32(smem4);
    const int m0 = (wid >> 1) * 32;          // warp m-range (b)
    const int n0 = (wid & 1) * 64;           // warp n-range (c)
    const int rowA = (lane & 7) + ((lane >> 3) & 1) * 8;
    const int uA = lane >> 4;
    const int rowB = (lane & 7) + (lane >> 4) * 8;
    const int uB = (lane >> 3) & 1;

    float accC[2][8][4];
    float accG[2][8][4];
#pragma unroll
    for (int mt = 0; mt < 2; mt++)
#pragma unroll
        for (int j = 0; j < 8; j++)
#pragma unroll
            for (int r = 0; r < 4; r++) { accC[mt][j][r] = 0.f; accG[mt][j][r] = 0.f; }

    // passes: hi*hi, lo*hi, hi*lo  (lo*lo term negligible: < 2^-18 relative)
    const int pa[3] = {0, 1, 0};   // ne/gr tile select (0=Hi, 1=Lo)
    const int pb[3] = {4, 4, 5};   // nw tile select    (4=Hi, 5=Lo)
#pragma unroll
    for (int p = 0; p < 3; p++) {
        uint32_t baseNe = sb0 + (uint32_t)(pa[p] * TILE_U4 * 16);
        uint32_t baseGr = sb0 + (uint32_t)((pa[p] + 2) * TILE_U4 * 16);
        uint32_t baseB  = sb0 + (uint32_t)(pb[p] * TILE_U4 * 16);
#pragma unroll 2
        for (int ks = 0; ks < 8; ks++) {
            uint32_t bf[8][2];
#pragma unroll
            for (int jp = 0; jp < 4; jp++) {
                uint32_t addr = baseB +
                    (uint32_t)(((n0 + jp * 16 + rowB) * ROW_U4 + ks * 2 + uB) * 16);
                ldsm_x4(bf[2 * jp][0], bf[2 * jp][1],
                        bf[2 * jp + 1][0], bf[2 * jp + 1][1], addr);
            }
            uint32_t an[2][4], ag[2][4];
#pragma unroll
            for (int mt = 0; mt < 2; mt++) {
                uint32_t aoff =
                    (uint32_t)(((m0 + mt * 16 + rowA) * ROW_U4 + ks * 2 + uA) * 16);
                ldsm_x4(an[mt][0], an[mt][1], an[mt][2], an[mt][3], baseNe + aoff);
                ldsm_x4(ag[mt][0], ag[mt][1], ag[mt][2], ag[mt][3], baseGr + aoff);
            }
#pragma unroll
            for (int mt = 0; mt < 2; mt++)
#pragma unroll
                for (int j = 0; j < 8; j++) {
                    mma16816(accC[mt][j], an[mt], bf[j]);
                    mma16816(accG[mt][j], ag[mt], bf[j]);
                }
        }
    }

    // ---- epilogue part 1: penalties + exp (kept in accC) + rowsum atomics --
    float* out_logit = out;
    float* out_pen = out + (size_t)Bdim * Cdim;
#pragma unroll
    for (int mt = 0; mt < 2; mt++) {
#pragma unroll
        for (int h = 0; h < 2; h++) {
            int b = bBase + m0 + mt * 16 + h * 8 + (lane >> 2);
            float sbv = g_s[b];
            int lb = labels[b];
            float esum = 0.f;
#pragma unroll
            for (int j = 0; j < 8; j++) {
                int c0 = cBase + n0 + j * 8 + (lane & 3) * 2;
                if (c0 < Cdim) {   // Cdim even, c0 even -> pair fully valid
                    float cv0 = accC[mt][j][h * 2 + 0];
                    float cv1 = accC[mt][j][h * 2 + 1];
                    float g0 = accG[mt][j][h * 2 + 0];
                    float g1 = accG[mt][j][h * 2 + 1];
                    float w0 = (sbv - cv0) * rsqrtf(fmaxf(2.f - 2.f * g0, EPS_F));
                    float w1 = (sbv - cv1) * rsqrtf(fmaxf(2.f - 2.f * g1, EPS_F));
                    if (c0 == lb) w0 = 0.f;       // dw == 0 exactly in reference
                    if (c0 + 1 == lb) w1 = 0.f;
                    float p0 = MARGIN_F - fminf(MARGIN_F, w0);
                    float p1 = MARGIN_F - fminf(MARGIN_F, w1);
                    float e0 = __expf(SCALE_F * cv0 - SCALE_F);
                    float e1 = __expf(SCALE_F * cv1 - SCALE_F);
                    accC[mt][j][h * 2 + 0] = e0;   // stash ev in registers
                    accC[mt][j][h * 2 + 1] = e1;
                    esum += e0 + e1;
                    *(float2*)&out_pen[(size_t)b * Cdim + c0] = make_float2(p0, p1);
                }
            }
            esum += __shfl_xor_sync(0xffffffffu, esum, 1);
            esum += __shfl_xor_sync(0xffffffffu, esum, 2);
            if ((lane & 3) == 0) atomicAdd(&g_rowsum[b], esum);
        }
    }

    // ---- grid-wide barrier (all 126 CTAs resident) ----
    __threadfence();
    __syncthreads();
    if (tid == 0) {
        atomicAdd(&g_count, 1);
        while (*(volatile int*)&g_count < NCTA) { }
    }
    __syncthreads();

    // ---- epilogue part 2: scaled logits ----
#pragma unroll
    for (int mt = 0; mt < 2; mt++) {
#pragma unroll
        for (int h = 0; h < 2; h++) {
            int b = bBase + m0 + mt * 16 + h * 8 + (lane >> 2);
            float inv = 1.f / __ldcg(&g_rowsum[b]);
#pragma unroll
            for (int j = 0; j < 8; j++) {
                int c0 = cBase + n0 + j * 8 + (lane & 3) * 2;
                if (c0 < Cdim) {
                    float e0 = accC[mt][j][h * 2 + 0] * inv;
                    float e1 = accC[mt][j][h * 2 + 1] * inv;
                    *(float2*)&out_logit[(size_t)b * Cdim + c0] =
                        make_float2(e0, e1);
                }
            }
        }
    }
}

// ---------------- launch ----------------
extern "C" void kernel_launch(void* const* d_in, const int* in_sizes, int n_in,
                              void* d_out, int out_size) {
    const float* embds = (const float*)d_in[0];   // [256,128]
    const float* w     = (const float*)d_in[1];   // [128,8000]
    const int* labels  = (const int*)d_in[2];     // [256]
    float* out = (float*)d_out;                   // logits then penalties

    const int kMainSmem = 6 * TILE_U4 * 16;       // 208896 B
    cudaFuncSetAttribute(k_main, cudaFuncAttributeMaxDynamicSharedMemorySize,
                         kMainSmem);

    k_prep<<<Bdim, Ddim>>>(embds, w, labels);

    dim3 g3(CPAD / 128, 2);                       // (63, 2) = 126 CTAs
    k_main<<<g3, 256, kMainSmem>>>(out, w, labels);
}

// round 8
// speedup vs baseline: 1.8841x; 1.1474x over previous
#include <cuda_runtime.h>
#include <cuda_bf16.h>
#include <cstdint>

#define Bdim 256
#define Ddim 128
#define Cdim 8000
#define CPAD 8064
#define SCALE_F 64.0f
#define MARGIN_F 0.5f
#define EPS_F 1e-12f
#define NCTA 126   // k_main grid (63 x 2); 1 CTA/SM, 148 SMs -> all co-resident
#define NTHR 512

// ---------------- device scratch (no allocations allowed) ----------------
__device__ uint4 g_neHi4[Bdim * 16];   // row = b, 16 x 16B of bf16 along k
__device__ uint4 g_neLo4[Bdim * 16];
__device__ uint4 g_grHi4[Bdim * 16];
__device__ uint4 g_grLo4[Bdim * 16];
__device__ float g_s[Bdim];
__device__ float g_rowsum[Bdim];
__device__ int g_count;

// ---------------- warp-MMA helpers (family-safe: ldmatrix + mma.sync) -------
__device__ __forceinline__ uint32_t smem_u32(const void* p) {
    uint32_t a;
    asm("{ .reg .u64 t; cvta.to.shared.u64 t, %1; cvt.u32.u64 %0, t; }"
        : "=r"(a) : "l"(p));
    return a;
}
__device__ __forceinline__ void ldsm_x4(uint32_t& r0, uint32_t& r1,
                                        uint32_t& r2, uint32_t& r3,
                                        uint32_t addr) {
    asm volatile(
        "ldmatrix.sync.aligned.m8n8.x4.shared.b16 {%0,%1,%2,%3}, [%4];"
        : "=r"(r0), "=r"(r1), "=r"(r2), "=r"(r3) : "r"(addr));
}
__device__ __forceinline__ void mma16816(float* d, const uint32_t* a,
                                         const uint32_t* b) {
    asm volatile(
        "mma.sync.aligned.m16n8k16.row.col.f32.bf16.bf16.f32 "
        "{%0,%1,%2,%3}, {%4,%5,%6,%7}, {%8,%9}, {%0,%1,%2,%3};"
        : "+f"(d[0]), "+f"(d[1]), "+f"(d[2]), "+f"(d[3])
        : "r"(a[0]), "r"(a[1]), "r"(a[2]), "r"(a[3]), "r"(b[0]), "r"(b[1]));
}

// smem tile geometry: 128 rows x 136 bf16 (272B rows -> 4-bank shift per row)
#define ROW_U4 17
#define TILE_U4 (128 * ROW_U4)           // 2176 uint4 = 34816 B
// layout: [0..4) ne/gr hi/lo tiles; [4..6) nw hi/lo tiles.
// The nw region (69632 B) doubles as the raw fp32 w staging area (65536 B).

// ---------------- K2: normalize embds, gather+normalize gr, splits, s[b] ----
__global__ void k_prep(const float* __restrict__ embds,
                       const float* __restrict__ w,
                       const int* __restrict__ labels) {
    int b = blockIdx.x;
    int d = threadIdx.x;  // 128 threads
    __shared__ float redA[4];
    __shared__ float redC[4];
    __shared__ float redB[4];

    float e = embds[b * Ddim + d];
    int lb = labels[b];
    float wv = w[d * Cdim + lb];

    float v = e * e;
    float ww = wv * wv;
#pragma unroll
    for (int o = 16; o > 0; o >>= 1) {
        v += __shfl_xor_sync(0xffffffffu, v, o);
        ww += __shfl_xor_sync(0xffffffffu, ww, o);
    }
    if ((d & 31) == 0) { redA[d >> 5] = v; redC[d >> 5] = ww; }
    __syncthreads();
    float ss = redA[0] + redA[1] + redA[2] + redA[3];
    float ss2 = redC[0] + redC[1] + redC[2] + redC[3];
    float ne = e * rsqrtf(fmaxf(ss, EPS_F));
    float gr = wv * rsqrtf(fmaxf(ss2, EPS_F));

    __nv_bfloat16 neh = __float2bfloat16(ne);
    __nv_bfloat16 nel = __float2bfloat16(ne - __bfloat162float(neh));
    __nv_bfloat16 grh = __float2bfloat16(gr);
    __nv_bfloat16 grl = __float2bfloat16(gr - __bfloat162float(grh));
    ((unsigned short*)g_neHi4)[b * 128 + d] = __bfloat16_as_ushort(neh);
    ((unsigned short*)g_neLo4)[b * 128 + d] = __bfloat16_as_ushort(nel);
    ((unsigned short*)g_grHi4)[b * 128 + d] = __bfloat16_as_ushort(grh);
    ((unsigned short*)g_grLo4)[b * 128 + d] = __bfloat16_as_ushort(grl);

    float sv = ne * gr;
#pragma unroll
    for (int o = 16; o > 0; o >>= 1) sv += __shfl_xor_sync(0xffffffffu, sv, o);
    if ((d & 31) == 0) redB[d >> 5] = sv;
    __syncthreads();
    if (d == 0) {
        g_s[b] = redB[0] + redB[1] + redB[2] + redB[3];
        g_rowsum[b] = 0.f;
        if (b == 0) g_count = 0;
    }
}

// ---------------- K3: fused w-normalize/split + dual GEMM + softmax ---------
// 512 threads (16 warps) for latency hiding; smem 204KB -> 1 CTA/SM.
__global__ __launch_bounds__(NTHR, 1) void k_main(float* __restrict__ out,
                                                  const float* __restrict__ w,
                                                  const int* __restrict__ labels) {
    extern __shared__ uint4 smem4[];
    __shared__ float red2[NTHR];
    __shared__ float sinv[128];
    const int tid = threadIdx.x;
    const int wid = tid >> 5;
    const int lane = tid & 31;
    const int cBase = blockIdx.x * 128;
    const int bBase = blockIdx.y * 128;

    // ---- stage ne/gr tiles + raw w chunk ----
    {
        const uint4* srcs[4] = {g_neHi4 + bBase * 16, g_neLo4 + bBase * 16,
                                g_grHi4 + bBase * 16, g_grLo4 + bBase * 16};
#pragma unroll
        for (int t4 = 0; t4 < 4; t4++) {
            const uint4* src = srcs[t4];
            uint4* dst = smem4 + t4 * TILE_U4;
#pragma unroll
            for (int i = 0; i < 4; i++) {
                int idx = tid + i * NTHR;
                dst[(idx >> 4) * ROW_U4 + (idx & 15)] = src[idx];
            }
        }
        // raw w chunk [k][c], plain 128x128 fp32, into the nw region
        float* raw = (float*)(smem4 + 4 * TILE_U4);
        int u = tid & 31;           // c quad
        int kb = tid >> 5;          // k group (16 groups of 8 rows)
        bool edge = (cBase + 128 > Cdim);
#pragma unroll 4
        for (int i = 0; i < 8; i++) {
            int k = kb * 8 + i;
            int c = cBase + u * 4;
            float4 v;
            if (!edge) {
                v = *(const float4*)&w[k * Cdim + c];
            } else {
                v.x = (c + 0 < Cdim) ? w[k * Cdim + c + 0] : 0.f;
                v.y = (c + 1 < Cdim) ? w[k * Cdim + c + 1] : 0.f;
                v.z = (c + 2 < Cdim) ? w[k * Cdim + c + 2] : 0.f;
                v.w = (c + 3 < Cdim) ? w[k * Cdim + c + 3] : 0.f;
            }
            *(float4*)&raw[k * 128 + u * 4] = v;
        }
    }
    __syncthreads();

    // ---- column norms of the raw chunk (conflict-free: bank = c % 32) ----
    {
        const float* raw = (const float*)(smem4 + 4 * TILE_U4);
        int c = tid & 127;
        int kq = tid >> 7;          // k quarter (0..3)
        float ss = 0.f;
#pragma unroll 8
        for (int k = kq * 32; k < kq * 32 + 32; k++) {
            float v = raw[k * 128 + c];
            ss = fmaf(v, v, ss);
        }
        red2[tid] = ss;
    }
    __syncthreads();
    if (tid < 128) {
        float r = rsqrtf(fmaxf(red2[tid] + red2[tid + 128] +
                               red2[tid + 256] + red2[tid + 384], EPS_F));
        sinv[tid] = r;
    }
    __syncthreads();

    // ---- in-place convert: raw fp32 -> bf16 hi/lo nw tiles (MMA layout) ----
    {
        const float* raw = (const float*)(smem4 + 4 * TILE_U4);
        int c = tid & 127;
        int kh = tid >> 7;          // 0..3, each owns 4 16B k-units
        float inv = sinv[c];
        uint4 hiu[4], lou[4];
#pragma unroll
        for (int q = 0; q < 4; q++) {
            int kq = kh * 4 + q;
            uint32_t hi[4], lo[4];
#pragma unroll
            for (int uu = 0; uu < 4; uu++) {
                float v0 = raw[(kq * 8 + uu * 2 + 0) * 128 + c] * inv;
                float v1 = raw[(kq * 8 + uu * 2 + 1) * 128 + c] * inv;
                __nv_bfloat16 h0 = __float2bfloat16(v0);
                __nv_bfloat16 h1 = __float2bfloat16(v1);
                __nv_bfloat16 l0 = __float2bfloat16(v0 - __bfloat162float(h0));
                __nv_bfloat16 l1 = __float2bfloat16(v1 - __bfloat162float(h1));
                hi[uu] = (uint32_t)__bfloat16_as_ushort(h0) |
                         ((uint32_t)__bfloat16_as_ushort(h1) << 16);
                lo[uu] = (uint32_t)__bfloat16_as_ushort(l0) |
                         ((uint32_t)__bfloat16_as_ushort(l1) << 16);
            }
            hiu[q] = make_uint4(hi[0], hi[1], hi[2], hi[3]);
            lou[q] = make_uint4(lo[0], lo[1], lo[2], lo[3]);
        }
        __syncthreads();   // all raw reads done before overwriting the region
        uint4* nwHi = smem4 + 4 * TILE_U4;
        uint4* nwLo = smem4 + 5 * TILE_U4;
#pragma unroll
        for (int q = 0; q < 4; q++) {
            int kq = kh * 4 + q;
            nwHi[c * ROW_U4 + kq] = hiu[q];
            nwLo[c * ROW_U4 + kq] = lou[q];
        }
    }
    __syncthreads();

    const uint32_t sb0 = smem_u32(smem4);
    const int m0 = (wid >> 2) * 32;          // warp m-range (b), 4 groups
    const int n0 = (wid & 3) * 32;           // warp n-range (c), 4 groups
    const int rowA = (lane & 7) + ((lane >> 3) & 1) * 8;
    const int uA = lane >> 4;
    const int rowB = (lane & 7) + (lane >> 4) * 8;
    const int uB = (lane >> 3) & 1;

    float accC[2][4][4];
    float accG[2][4][4];
#pragma unroll
    for (int mt = 0; mt < 2; mt++)
#pragma unroll
        for (int j = 0; j < 4; j++)
#pragma unroll
            for (int r = 0; r < 4; r++) { accC[mt][j][r] = 0.f; accG[mt][j][r] = 0.f; }

    // passes: hi*hi, lo*hi, hi*lo  (lo*lo term negligible: < 2^-18 relative)
    const int pa[3] = {0, 1, 0};   // ne/gr tile select (0=Hi, 1=Lo)
    const int pb[3] = {4, 4, 5};   // nw tile select    (4=Hi, 5=Lo)
#pragma unroll
    for (int p = 0; p < 3; p++) {
        uint32_t baseNe = sb0 + (uint32_t)(pa[p] * TILE_U4 * 16);
        uint32_t baseGr = sb0 + (uint32_t)((pa[p] + 2) * TILE_U4 * 16);
        uint32_t baseB  = sb0 + (uint32_t)(pb[p] * TILE_U4 * 16);
#pragma unroll 2
        for (int ks = 0; ks < 8; ks++) {
            uint32_t bf[4][2];
#pragma unroll
            for (int jp = 0; jp < 2; jp++) {
                uint32_t addr = baseB +
                    (uint32_t)(((n0 + jp * 16 + rowB) * ROW_U4 + ks * 2 + uB) * 16);
                ldsm_x4(bf[2 * jp][0], bf[2 * jp][1],
                        bf[2 * jp + 1][0], bf[2 * jp + 1][1], addr);
            }
            uint32_t an[2][4], ag[2][4];
#pragma unroll
            for (int mt = 0; mt < 2; mt++) {
                uint32_t aoff =
                    (uint32_t)(((m0 + mt * 16 + rowA) * ROW_U4 + ks * 2 + uA) * 16);
                ldsm_x4(an[mt][0], an[mt][1], an[mt][2], an[mt][3], baseNe + aoff);
                ldsm_x4(ag[mt][0], ag[mt][1], ag[mt][2], ag[mt][3], baseGr + aoff);
            }
#pragma unroll
            for (int mt = 0; mt < 2; mt++)
#pragma unroll
                for (int j = 0; j < 4; j++) {
                    mma16816(accC[mt][j], an[mt], bf[j]);
                    mma16816(accG[mt][j], ag[mt], bf[j]);
                }
        }
    }

    // ---- epilogue part 1: penalties + exp (kept in accC) + rowsum atomics --
    float* out_logit = out;
    float* out_pen = out + (size_t)Bdim * Cdim;
#pragma unroll
    for (int mt = 0; mt < 2; mt++) {
#pragma unroll
        for (int h = 0; h < 2; h++) {
            int b = bBase + m0 + mt * 16 + h * 8 + (lane >> 2);
            float sbv = g_s[b];
            int lb = labels[b];
            float esum = 0.f;
#pragma unroll
            for (int j = 0; j < 4; j++) {
                int c0 = cBase + n0 + j * 8 + (lane & 3) * 2;
                if (c0 < Cdim) {   // Cdim even, c0 even -> pair fully valid
                    float cv0 = accC[mt][j][h * 2 + 0];
                    float cv1 = accC[mt][j][h * 2 + 1];
                    float g0 = accG[mt][j][h * 2 + 0];
                    float g1 = accG[mt][j][h * 2 + 1];
                    float w0 = (sbv - cv0) * rsqrtf(fmaxf(2.f - 2.f * g0, EPS_F));
                    float w1 = (sbv - cv1) * rsqrtf(fmaxf(2.f - 2.f * g1, EPS_F));
                    if (c0 == lb) w0 = 0.f;       // dw == 0 exactly in reference
                    if (c0 + 1 == lb) w1 = 0.f;
                    float p0 = MARGIN_F - fminf(MARGIN_F, w0);
                    float p1 = MARGIN_F - fminf(MARGIN_F, w1);
                    float e0 = __expf(SCALE_F * cv0 - SCALE_F);
                    float e1 = __expf(SCALE_F * cv1 - SCALE_F);
                    accC[mt][j][h * 2 + 0] = e0;   // stash ev in registers
                    accC[mt][j][h * 2 + 1] = e1;
                    esum += e0 + e1;
                    *(float2*)&out_pen[(size_t)b * Cdim + c0] = make_float2(p0, p1);
                }
            }
            esum += __shfl_xor_sync(0xffffffffu, esum, 1);
            esum += __shfl_xor_sync(0xffffffffu, esum, 2);
            if ((lane & 3) == 0) atomicAdd(&g_rowsum[b], esum);
        }
    }

    // ---- grid-wide barrier (all 126 CTAs resident) ----
    __threadfence();
    __syncthreads();
    if (tid == 0) {
        atomicAdd(&g_count, 1);
        while (*(volatile int*)&g_count < NCTA) { }
    }
    __syncthreads();

    // ---- epilogue part 2: scaled logits ----
#pragma unroll
    for (int mt = 0; mt < 2; mt++) {
#pragma unroll
        for (int h = 0; h < 2; h++) {
            int b = bBase + m0 + mt * 16 + h * 8 + (lane >> 2);
            float inv = 1.f / __ldcg(&g_rowsum[b]);
#pragma unroll
            for (int j = 0; j < 4; j++) {
                int c0 = cBase + n0 + j * 8 + (lane & 3) * 2;
                if (c0 < Cdim) {
                    float e0 = accC[mt][j][h * 2 + 0] * inv;
                    float e1 = accC[mt][j][h * 2 + 1] * inv;
                    *(float2*)&out_logit[(size_t)b * Cdim + c0] =
                        make_float2(e0, e1);
                }
            }
        }
    }
}

// ---------------- launch ----------------
extern "C" void kernel_launch(void* const* d_in, const int* in_sizes, int n_in,
                              void* d_out, int out_size) {
    const float* embds = (const float*)d_in[0];   // [256,128]
    const float* w     = (const float*)d_in[1];   // [128,8000]
    const int* labels  = (const int*)d_in[2];     // [256]
    float* out = (float*)d_out;                   // logits then penalties

    const int kMainSmem = 6 * TILE_U4 * 16;       // 208896 B
    cudaFuncSetAttribute(k_main, cudaFuncAttributeMaxDynamicSharedMemorySize,
                         kMainSmem);

    k_prep<<<Bdim, Ddim>>>(embds, w, labels);

    dim3 g3(CPAD / 128, 2);                       // (63, 2) = 126 CTAs
    k_main<<<g3, NTHR, kMainSmem>>>(out, w, labels);
}

// round 9
// speedup vs baseline: 1.8913x; 1.0038x over previous
#include <cuda_runtime.h>
#include <cuda_bf16.h>
#include <cstdint>

#define Bdim 256
#define Ddim 128
#define Cdim 8000
#define CPAD 8064
#define SCALE_F 64.0f
#define MARGIN_F 0.5f
#define EPS_F 1e-12f
#define NCTA 126   // k_main grid (63 x 2); 1 CTA/SM, 148 SMs -> all co-resident
#define NTHR 512

// ---------------- device scratch (no allocations allowed) ----------------
__device__ uint4 g_neHi4[Bdim * 16];   // row = b, 16 x 16B of bf16 along k
__device__ uint4 g_neLo4[Bdim * 16];
__device__ uint4 g_grHi4[Bdim * 16];
__device__ uint4 g_grLo4[Bdim * 16];
__device__ float g_s[Bdim];
__device__ float g_rowsum[Bdim];
__device__ int g_count;

// ---------------- warp-MMA helpers (family-safe: ldmatrix + mma.sync) -------
__device__ __forceinline__ uint32_t smem_u32(const void* p) {
    uint32_t a;
    asm("{ .reg .u64 t; cvta.to.shared.u64 t, %1; cvt.u32.u64 %0, t; }"
        : "=r"(a) : "l"(p));
    return a;
}
__device__ __forceinline__ void ldsm_x4(uint32_t& r0, uint32_t& r1,
                                        uint32_t& r2, uint32_t& r3,
                                        uint32_t addr) {
    asm volatile(
        "ldmatrix.sync.aligned.m8n8.x4.shared.b16 {%0,%1,%2,%3}, [%4];"
        : "=r"(r0), "=r"(r1), "=r"(r2), "=r"(r3) : "r"(addr));
}
__device__ __forceinline__ void mma16816(float* d, const uint32_t* a,
                                         const uint32_t* b) {
    asm volatile(
        "mma.sync.aligned.m16n8k16.row.col.f32.bf16.bf16.f32 "
        "{%0,%1,%2,%3}, {%4,%5,%6,%7}, {%8,%9}, {%0,%1,%2,%3};"
        : "+f"(d[0]), "+f"(d[1]), "+f"(d[2]), "+f"(d[3])
        : "r"(a[0]), "r"(a[1]), "r"(a[2]), "r"(a[3]), "r"(b[0]), "r"(b[1]));
}

// smem tile geometry: 128 rows x 136 bf16 (272B rows -> 4-bank shift per row)
#define ROW_U4 17
#define TILE_U4 (128 * ROW_U4)           // 2176 uint4 = 34816 B
// layout: [0..4) ne/gr hi/lo tiles; [4..6) nw hi/lo tiles.

// ---------------- K2: normalize embds, gather+normalize gr, splits, s[b] ----
__global__ void k_prep(const float* __restrict__ embds,
                       const float* __restrict__ w,
                       const int* __restrict__ labels) {
    int b = blockIdx.x;
    int d = threadIdx.x;  // 128 threads
    __shared__ float redA[4];
    __shared__ float redC[4];
    __shared__ float redB[4];

    float e = embds[b * Ddim + d];
    int lb = labels[b];
    float wv = w[d * Cdim + lb];

    float v = e * e;
    float ww = wv * wv;
#pragma unroll
    for (int o = 16; o > 0; o >>= 1) {
        v += __shfl_xor_sync(0xffffffffu, v, o);
        ww += __shfl_xor_sync(0xffffffffu, ww, o);
    }
    if ((d & 31) == 0) { redA[d >> 5] = v; redC[d >> 5] = ww; }
    __syncthreads();
    float ss = redA[0] + redA[1] + redA[2] + redA[3];
    float ss2 = redC[0] + redC[1] + redC[2] + redC[3];
    float ne = e * rsqrtf(fmaxf(ss, EPS_F));
    float gr = wv * rsqrtf(fmaxf(ss2, EPS_F));

    __nv_bfloat16 neh = __float2bfloat16(ne);
    __nv_bfloat16 nel = __float2bfloat16(ne - __bfloat162float(neh));
    __nv_bfloat16 grh = __float2bfloat16(gr);
    __nv_bfloat16 grl = __float2bfloat16(gr - __bfloat162float(grh));
    ((unsigned short*)g_neHi4)[b * 128 + d] = __bfloat16_as_ushort(neh);
    ((unsigned short*)g_neLo4)[b * 128 + d] = __bfloat16_as_ushort(nel);
    ((unsigned short*)g_grHi4)[b * 128 + d] = __bfloat16_as_ushort(grh);
    ((unsigned short*)g_grLo4)[b * 128 + d] = __bfloat16_as_ushort(grl);

    float sv = ne * gr;
#pragma unroll
    for (int o = 16; o > 0; o >>= 1) sv += __shfl_xor_sync(0xffffffffu, sv, o);
    if ((d & 31) == 0) redB[d >> 5] = sv;
    __syncthreads();
    if (d == 0) {
        g_s[b] = redB[0] + redB[1] + redB[2] + redB[3];
        g_rowsum[b] = 0.f;
        if (b == 0) g_count = 0;
    }
}

// ---------------- K3: fused w-normalize/split + dual GEMM + softmax ---------
// 512 threads (16 warps); smem 204KB -> 1 CTA/SM. w is register-staged:
// no raw fp32 smem round-trips before the MMA.
__global__ __launch_bounds__(NTHR, 1) void k_main(float* __restrict__ out,
                                                  const float* __restrict__ w,
                                                  const int* __restrict__ labels) {
    extern __shared__ uint4 smem4[];
    __shared__ float red2[NTHR];
    __shared__ float sinv[128];
    const int tid = threadIdx.x;
    const int wid = tid >> 5;
    const int lane = tid & 31;
    const int cBase = blockIdx.x * 128;
    const int bBase = blockIdx.y * 128;

    // ---- load w column chunk straight into registers ----
    // thread owns (c = tid & 127, k-quarter = tid >> 7): 32 k-strided scalar
    // LDGs; consecutive lanes = consecutive c -> fully coalesced 128B lines.
    const int c = tid & 127;
    const int kq = tid >> 7;            // 0..3
    float wv[32];
    {
        int cCol = cBase + c;
        if (cCol < Cdim) {
            const float* wp = w + (size_t)(kq * 32) * Cdim + cCol;
#pragma unroll
            for (int i = 0; i < 32; i++) wv[i] = wp[(size_t)i * Cdim];
        } else {
#pragma unroll
            for (int i = 0; i < 32; i++) wv[i] = 0.f;
        }
    }

    // ---- stage ne/gr tiles (independent of the w loads above) ----
    {
        const uint4* srcs[4] = {g_neHi4 + bBase * 16, g_neLo4 + bBase * 16,
                                g_grHi4 + bBase * 16, g_grLo4 + bBase * 16};
#pragma unroll
        for (int t4 = 0; t4 < 4; t4++) {
            const uint4* src = srcs[t4];
            uint4* dst = smem4 + t4 * TILE_U4;
#pragma unroll
            for (int i = 0; i < 4; i++) {
                int idx = tid + i * NTHR;
                dst[(idx >> 4) * ROW_U4 + (idx & 15)] = src[idx];
            }
        }
    }

    // ---- column norm partials from registers ----
    {
        float ss = 0.f;
#pragma unroll
        for (int i = 0; i < 32; i++) ss = fmaf(wv[i], wv[i], ss);
        red2[tid] = ss;
    }
    __syncthreads();   // red2 ready + ne/gr tiles staged
    if (tid < 128) {
        sinv[tid] = rsqrtf(fmaxf(red2[tid] + red2[tid + 128] +
                                 red2[tid + 256] + red2[tid + 384], EPS_F));
    }
    __syncthreads();

    // ---- convert registers -> bf16 hi/lo nw tiles (MMA layout) ----
    {
        float inv = sinv[c];
        uint4* nwHi = smem4 + 4 * TILE_U4;
        uint4* nwLo = smem4 + 5 * TILE_U4;
#pragma unroll
        for (int q = 0; q < 4; q++) {       // 4 16B k-units of 8 bf16
            uint32_t hi[4], lo[4];
#pragma unroll
            for (int uu = 0; uu < 4; uu++) {
                float v0 = wv[q * 8 + uu * 2 + 0] * inv;
                float v1 = wv[q * 8 + uu * 2 + 1] * inv;
                __nv_bfloat16 h0 = __float2bfloat16(v0);
                __nv_bfloat16 h1 = __float2bfloat16(v1);
                __nv_bfloat16 l0 = __float2bfloat16(v0 - __bfloat162float(h0));
                __nv_bfloat16 l1 = __float2bfloat16(v1 - __bfloat162float(h1));
                hi[uu] = (uint32_t)__bfloat16_as_ushort(h0) |
                         ((uint32_t)__bfloat16_as_ushort(h1) << 16);
                lo[uu] = (uint32_t)__bfloat16_as_ushort(l0) |
                         ((uint32_t)__bfloat16_as_ushort(l1) << 16);
            }
            int kunit = kq * 4 + q;
            nwHi[c * ROW_U4 + kunit] = make_uint4(hi[0], hi[1], hi[2], hi[3]);
            nwLo[c * ROW_U4 + kunit] = make_uint4(lo[0], lo[1], lo[2], lo[3]);
        }
    }
    __syncthreads();

    const uint32_t sb0 = smem_u32(smem4);
    const int m0 = (wid >> 2) * 32;          // warp m-range (b), 4 groups
    const int n0 = (wid & 3) * 32;           // warp n-range (c), 4 groups
    const int rowA = (lane & 7) + ((lane >> 3) & 1) * 8;
    const int uA = lane >> 4;
    const int rowB = (lane & 7) + (lane >> 4) * 8;
    const int uB = (lane >> 3) & 1;

    float accC[2][4][4];
    float accG[2][4][4];
#pragma unroll
    for (int mt = 0; mt < 2; mt++)
#pragma unroll
        for (int j = 0; j < 4; j++)
#pragma unroll
            for (int r = 0; r < 4; r++) { accC[mt][j][r] = 0.f; accG[mt][j][r] = 0.f; }

    // passes: hi*hi, lo*hi, hi*lo  (lo*lo term negligible: < 2^-18 relative)
    const int pa[3] = {0, 1, 0};   // ne/gr tile select (0=Hi, 1=Lo)
    const int pb[3] = {4, 4, 5};   // nw tile select    (4=Hi, 5=Lo)
#pragma unroll
    for (int p = 0; p < 3; p++) {
        uint32_t baseNe = sb0 + (uint32_t)(pa[p] * TILE_U4 * 16);
        uint32_t baseGr = sb0 + (uint32_t)((pa[p] + 2) * TILE_U4 * 16);
        uint32_t baseB  = sb0 + (uint32_t)(pb[p] * TILE_U4 * 16);
#pragma unroll 2
        for (int ks = 0; ks < 8; ks++) {
            uint32_t bf[4][2];
#pragma unroll
            for (int jp = 0; jp < 2; jp++) {
                uint32_t addr = baseB +
                    (uint32_t)(((n0 + jp * 16 + rowB) * ROW_U4 + ks * 2 + uB) * 16);
                ldsm_x4(bf[2 * jp][0], bf[2 * jp][1],
                        bf[2 * jp + 1][0], bf[2 * jp + 1][1], addr);
            }
            uint32_t an[2][4], ag[2][4];
#pragma unroll
            for (int mt = 0; mt < 2; mt++) {
                uint32_t aoff =
                    (uint32_t)(((m0 + mt * 16 + rowA) * ROW_U4 + ks * 2 + uA) * 16);
                ldsm_x4(an[mt][0], an[mt][1], an[mt][2], an[mt][3], baseNe + aoff);
                ldsm_x4(ag[mt][0], ag[mt][1], ag[mt][2], ag[mt][3], baseGr + aoff);
            }
#pragma unroll
            for (int mt = 0; mt < 2; mt++)
#pragma unroll
                for (int j = 0; j < 4; j++) {
                    mma16816(accC[mt][j], an[mt], bf[j]);
                    mma16816(accG[mt][j], ag[mt], bf[j]);
                }
        }
    }

    // ---- epilogue part 1: penalties + exp (kept in accC) + rowsum atomics --
    float* out_logit = out;
    float* out_pen = out + (size_t)Bdim * Cdim;
#pragma unroll
    for (int mt = 0; mt < 2; mt++) {
#pragma unroll
        for (int h = 0; h < 2; h++) {
            int b = bBase + m0 + mt * 16 + h * 8 + (lane >> 2);
            float sbv = g_s[b];
            int lb = labels[b];
            float esum = 0.f;
#pragma unroll
            for (int j = 0; j < 4; j++) {
                int c0 = cBase + n0 + j * 8 + (lane & 3) * 2;
                if (c0 < Cdim) {   // Cdim even, c0 even -> pair fully valid
                    float cv0 = accC[mt][j][h * 2 + 0];
                    float cv1 = accC[mt][j][h * 2 + 1];
                    float g0 = accG[mt][j][h * 2 + 0];
                    float g1 = accG[mt][j][h * 2 + 1];
                    float w0 = (sbv - cv0) * rsqrtf(fmaxf(2.f - 2.f * g0, EPS_F));
                    float w1 = (sbv - cv1) * rsqrtf(fmaxf(2.f - 2.f * g1, EPS_F));
                    if (c0 == lb) w0 = 0.f;       // dw == 0 exactly in reference
                    if (c0 + 1 == lb) w1 = 0.f;
                    float p0 = MARGIN_F - fminf(MARGIN_F, w0);
                    float p1 = MARGIN_F - fminf(MARGIN_F, w1);
                    float e0 = __expf(SCALE_F * cv0 - SCALE_F);
                    float e1 = __expf(SCALE_F * cv1 - SCALE_F);
                    accC[mt][j][h * 2 + 0] = e0;   // stash ev in registers
                    accC[mt][j][h * 2 + 1] = e1;
                    esum += e0 + e1;
                    *(float2*)&out_pen[(size_t)b * Cdim + c0] = make_float2(p0, p1);
                }
            }
            esum += __shfl_xor_sync(0xffffffffu, esum, 1);
            esum += __shfl_xor_sync(0xffffffffu, esum, 2);
            if ((lane & 3) == 0) atomicAdd(&g_rowsum[b], esum);
        }
    }

    // ---- grid-wide barrier (all 126 CTAs resident) ----
    __threadfence();
    __syncthreads();
    if (tid == 0) {
        atomicAdd(&g_count, 1);
        while (*(volatile int*)&g_count < NCTA) { }
    }
    __syncthreads();

    // ---- epilogue part 2: scaled logits ----
#pragma unroll
    for (int mt = 0; mt < 2; mt++) {
#pragma unroll
        for (int h = 0; h < 2; h++) {
            int b = bBase + m0 + mt * 16 + h * 8 + (lane >> 2);
            float inv = 1.f / __ldcg(&g_rowsum[b]);
#pragma unroll
            for (int j = 0; j < 4; j++) {
                int c0 = cBase + n0 + j * 8 + (lane & 3) * 2;
                if (c0 < Cdim) {
                    float e0 = accC[mt][j][h * 2 + 0] * inv;
                    float e1 = accC[mt][j][h * 2 + 1] * inv;
                    *(float2*)&out_logit[(size_t)b * Cdim + c0] =
                        make_float2(e0, e1);
                }
            }
        }
    }
}

// ---------------- launch ----------------
extern "C" void kernel_launch(void* const* d_in, const int* in_sizes, int n_in,
                              void* d_out, int out_size) {
    const float* embds = (const float*)d_in[0];   // [256,128]
    const float* w     = (const float*)d_in[1];   // [128,8000]
    const int* labels  = (const int*)d_in[2];     // [256]
    float* out = (float*)d_out;                   // logits then penalties

    const int kMainSmem = 6 * TILE_U4 * 16;       // 208896 B
    cudaFuncSetAttribute(k_main, cudaFuncAttributeMaxDynamicSharedMemorySize,
                         kMainSmem);

    k_prep<<<Bdim, Ddim>>>(embds, w, labels);

    dim3 g3(CPAD / 128, 2);                       // (63, 2) = 126 CTAs
    k_main<<<g3, NTHR, kMainSmem>>>(out, w, labels);
}

// round 10
// speedup vs baseline: 2.0807x; 1.1001x over previous
#include <cuda_runtime.h>
#include <cuda_bf16.h>
#include <cstdint>

#define Bdim 256
#define Ddim 128
#define Cdim 8000
#define CPAD 8064
#define SCALE_F 64.0f
#define MARGIN_F 0.5f
#define EPS_F 1e-12f
#define NCTA 126   // k_main grid (63 x 2); 1 CTA/SM, 148 SMs -> all co-resident
#define NTHR 512

// ---------------- device scratch (no allocations allowed) ----------------
__device__ uint4 g_neHi4[Bdim * 16];   // row = b, 16 x 16B of bf16 along k
__device__ uint4 g_neLo4[Bdim * 16];
__device__ uint4 g_grHi4[Bdim * 16];
__device__ uint4 g_grLo4[Bdim * 16];
__device__ float g_s[Bdim];
__device__ float g_rowsum[Bdim];
__device__ int g_count;

// ---------------- warp-MMA helpers (family-safe: ldmatrix + mma.sync) -------
__device__ __forceinline__ uint32_t smem_u32(const void* p) {
    uint32_t a;
    asm("{ .reg .u64 t; cvta.to.shared.u64 t, %1; cvt.u32.u64 %0, t; }"
        : "=r"(a) : "l"(p));
    return a;
}
__device__ __forceinline__ void ldsm_x4(uint32_t& r0, uint32_t& r1,
                                        uint32_t& r2, uint32_t& r3,
                                        uint32_t addr) {
    asm volatile(
        "ldmatrix.sync.aligned.m8n8.x4.shared.b16 {%0,%1,%2,%3}, [%4];"
        : "=r"(r0), "=r"(r1), "=r"(r2), "=r"(r3) : "r"(addr));
}
__device__ __forceinline__ void mma16816(float* d, const uint32_t* a,
                                         const uint32_t* b) {
    asm volatile(
        "mma.sync.aligned.m16n8k16.row.col.f32.bf16.bf16.f32 "
        "{%0,%1,%2,%3}, {%4,%5,%6,%7}, {%8,%9}, {%0,%1,%2,%3};"
        : "+f"(d[0]), "+f"(d[1]), "+f"(d[2]), "+f"(d[3])
        : "r"(a[0]), "r"(a[1]), "r"(a[2]), "r"(a[3]), "r"(b[0]), "r"(b[1]));
}

// smem tile geometry: 128 rows x 136 bf16 (272B rows -> 4-bank shift per row)
#define ROW_U4 17
#define TILE_U4 (128 * ROW_U4)           // 2176 uint4 = 34816 B
// layout: [0..4) ne/gr hi/lo tiles; [4..6) nw hi/lo tiles.

// ---------------- K2: normalize embds, gather+normalize gr, splits, s[b] ----
__global__ void k_prep(const float* __restrict__ embds,
                       const float* __restrict__ w,
                       const int* __restrict__ labels) {
    int b = blockIdx.x;
    int d = threadIdx.x;  // 128 threads
    __shared__ float redA[4];
    __shared__ float redC[4];
    __shared__ float redB[4];

    float e = embds[b * Ddim + d];
    int lb = labels[b];
    float wv = w[d * Cdim + lb];

    float v = e * e;
    float ww = wv * wv;
#pragma unroll
    for (int o = 16; o > 0; o >>= 1) {
        v += __shfl_xor_sync(0xffffffffu, v, o);
        ww += __shfl_xor_sync(0xffffffffu, ww, o);
    }
    if ((d & 31) == 0) { redA[d >> 5] = v; redC[d >> 5] = ww; }
    __syncthreads();
    float ss = redA[0] + redA[1] + redA[2] + redA[3];
    float ss2 = redC[0] + redC[1] + redC[2] + redC[3];
    float ne = e * rsqrtf(fmaxf(ss, EPS_F));
    float gr = wv * rsqrtf(fmaxf(ss2, EPS_F));

    __nv_bfloat16 neh = __float2bfloat16(ne);
    __nv_bfloat16 nel = __float2bfloat16(ne - __bfloat162float(neh));
    __nv_bfloat16 grh = __float2bfloat16(gr);
    __nv_bfloat16 grl = __float2bfloat16(gr - __bfloat162float(grh));
    ((unsigned short*)g_neHi4)[b * 128 + d] = __bfloat16_as_ushort(neh);
    ((unsigned short*)g_neLo4)[b * 128 + d] = __bfloat16_as_ushort(nel);
    ((unsigned short*)g_grHi4)[b * 128 + d] = __bfloat16_as_ushort(grh);
    ((unsigned short*)g_grLo4)[b * 128 + d] = __bfloat16_as_ushort(grl);

    float sv = ne * gr;
#pragma unroll
    for (int o = 16; o > 0; o >>= 1) sv += __shfl_xor_sync(0xffffffffu, sv, o);
    if ((d & 31) == 0) redB[d >> 5] = sv;
    __syncthreads();
    if (d == 0) {
        g_s[b] = redB[0] + redB[1] + redB[2] + redB[3];
        g_rowsum[b] = 0.f;
        if (b == 0) g_count = 0;
    }
}

// ---------------- K3: fused w-normalize/split + dual GEMM + softmax ---------
// 512 threads (16 warps); smem 204KB -> 1 CTA/SM. w is register-staged.
__global__ __launch_bounds__(NTHR, 1) void k_main(float* __restrict__ out,
                                                  const float* __restrict__ w,
                                                  const int* __restrict__ labels) {
    extern __shared__ uint4 smem4[];
    __shared__ float red2[NTHR];
    __shared__ float sinv[128];
    __shared__ float sRow[128];    // per-CTA rowsum accumulator, then 1/rowsum
    const int tid = threadIdx.x;
    const int wid = tid >> 5;
    const int lane = tid & 31;
    const int cBase = blockIdx.x * 128;
    const int bBase = blockIdx.y * 128;

    // ---- load w column chunk straight into registers ----
    const int c = tid & 127;
    const int kq = tid >> 7;            // 0..3
    float wv[32];
    {
        int cCol = cBase + c;
        if (cCol < Cdim) {
            const float* wp = w + (size_t)(kq * 32) * Cdim + cCol;
#pragma unroll
            for (int i = 0; i < 32; i++) wv[i] = wp[(size_t)i * Cdim];
        } else {
#pragma unroll
            for (int i = 0; i < 32; i++) wv[i] = 0.f;
        }
    }

    // ---- stage ne/gr tiles (independent of the w loads above) ----
    {
        const uint4* srcs[4] = {g_neHi4 + bBase * 16, g_neLo4 + bBase * 16,
                                g_grHi4 + bBase * 16, g_grLo4 + bBase * 16};
#pragma unroll
        for (int t4 = 0; t4 < 4; t4++) {
            const uint4* src = srcs[t4];
            uint4* dst = smem4 + t4 * TILE_U4;
#pragma unroll
            for (int i = 0; i < 4; i++) {
                int idx = tid + i * NTHR;
                dst[(idx >> 4) * ROW_U4 + (idx & 15)] = src[idx];
            }
        }
    }

    // ---- column norm partials from registers ----
    {
        float ss = 0.f;
#pragma unroll
        for (int i = 0; i < 32; i++) ss = fmaf(wv[i], wv[i], ss);
        red2[tid] = ss;
    }
    __syncthreads();   // red2 ready + ne/gr tiles staged
    if (tid < 128) {
        sinv[tid] = rsqrtf(fmaxf(red2[tid] + red2[tid + 128] +
                                 red2[tid + 256] + red2[tid + 384], EPS_F));
        sRow[tid] = 0.f;
    }
    __syncthreads();

    // ---- convert registers -> bf16 hi/lo nw tiles (MMA layout) ----
    {
        float inv = sinv[c];
        uint4* nwHi = smem4 + 4 * TILE_U4;
        uint4* nwLo = smem4 + 5 * TILE_U4;
#pragma unroll
        for (int q = 0; q < 4; q++) {       // 4 16B k-units of 8 bf16
            uint32_t hi[4], lo[4];
#pragma unroll
            for (int uu = 0; uu < 4; uu++) {
                float v0 = wv[q * 8 + uu * 2 + 0] * inv;
                float v1 = wv[q * 8 + uu * 2 + 1] * inv;
                __nv_bfloat16 h0 = __float2bfloat16(v0);
                __nv_bfloat16 h1 = __float2bfloat16(v1);
                __nv_bfloat16 l0 = __float2bfloat16(v0 - __bfloat162float(h0));
                __nv_bfloat16 l1 = __float2bfloat16(v1 - __bfloat162float(h1));
                hi[uu] = (uint32_t)__bfloat16_as_ushort(h0) |
                         ((uint32_t)__bfloat16_as_ushort(h1) << 16);
                lo[uu] = (uint32_t)__bfloat16_as_ushort(l0) |
                         ((uint32_t)__bfloat16_as_ushort(l1) << 16);
            }
            int kunit = kq * 4 + q;
            nwHi[c * ROW_U4 + kunit] = make_uint4(hi[0], hi[1], hi[2], hi[3]);
            nwLo[c * ROW_U4 + kunit] = make_uint4(lo[0], lo[1], lo[2], lo[3]);
        }
    }
    __syncthreads();

    const uint32_t sb0 = smem_u32(smem4);
    const int m0 = (wid >> 2) * 32;          // warp m-range (b), 4 groups
    const int n0 = (wid & 3) * 32;           // warp n-range (c), 4 groups
    const int rowA = (lane & 7) + ((lane >> 3) & 1) * 8;
    const int uA = lane >> 4;
    const int rowB = (lane & 7) + (lane >> 4) * 8;
    const int uB = (lane >> 3) & 1;

    float accC[2][4][4];
    float accG[2][4][4];
#pragma unroll
    for (int mt = 0; mt < 2; mt++)
#pragma unroll
        for (int j = 0; j < 4; j++)
#pragma unroll
            for (int r = 0; r < 4; r++) { accC[mt][j][r] = 0.f; accG[mt][j][r] = 0.f; }

    // ks-outer loop: per ks, B-hi/B-lo loaded once; 3 split-pass combos
    // (hi*hi, lo*hi, hi*lo; lo*lo < 2^-18 relative, omitted) issued inline.
    const uint32_t baseNeHi = sb0;
    const uint32_t baseNeLo = sb0 + (uint32_t)(1 * TILE_U4 * 16);
    const uint32_t baseGrHi = sb0 + (uint32_t)(2 * TILE_U4 * 16);
    const uint32_t baseGrLo = sb0 + (uint32_t)(3 * TILE_U4 * 16);
    const uint32_t baseBHi  = sb0 + (uint32_t)(4 * TILE_U4 * 16);
    const uint32_t baseBLo  = sb0 + (uint32_t)(5 * TILE_U4 * 16);
#pragma unroll
    for (int ks = 0; ks < 8; ks++) {
        uint32_t bfH[4][2], bfL[4][2];
#pragma unroll
        for (int jp = 0; jp < 2; jp++) {
            uint32_t boff =
                (uint32_t)(((n0 + jp * 16 + rowB) * ROW_U4 + ks * 2 + uB) * 16);
            ldsm_x4(bfH[2 * jp][0], bfH[2 * jp][1],
                    bfH[2 * jp + 1][0], bfH[2 * jp + 1][1], baseBHi + boff);
            ldsm_x4(bfL[2 * jp][0], bfL[2 * jp][1],
                    bfL[2 * jp + 1][0], bfL[2 * jp + 1][1], baseBLo + boff);
        }
#pragma unroll
        for (int mt = 0; mt < 2; mt++) {
            uint32_t aoff =
                (uint32_t)(((m0 + mt * 16 + rowA) * ROW_U4 + ks * 2 + uA) * 16);
            uint32_t anH[4], anL[4], agH[4], agL[4];
            ldsm_x4(anH[0], anH[1], anH[2], anH[3], baseNeHi + aoff);
            ldsm_x4(anL[0], anL[1], anL[2], anL[3], baseNeLo + aoff);
            ldsm_x4(agH[0], agH[1], agH[2], agH[3], baseGrHi + aoff);
            ldsm_x4(agL[0], agL[1], agL[2], agL[3], baseGrLo + aoff);
#pragma unroll
            for (int j = 0; j < 4; j++) {
                mma16816(accC[mt][j], anH, bfH[j]);
                mma16816(accG[mt][j], agH, bfH[j]);
                mma16816(accC[mt][j], anL, bfH[j]);
                mma16816(accG[mt][j], agL, bfH[j]);
                mma16816(accC[mt][j], anH, bfL[j]);
                mma16816(accG[mt][j], agH, bfL[j]);
            }
        }
    }

    // ---- epilogue part 1: penalties + exp (kept in accC) + smem rowsums ----
    float* out_logit = out;
    float* out_pen = out + (size_t)Bdim * Cdim;
#pragma unroll
    for (int mt = 0; mt < 2; mt++) {
#pragma unroll
        for (int h = 0; h < 2; h++) {
            int row = m0 + mt * 16 + h * 8 + (lane >> 2);
            int b = bBase + row;
            float sbv = g_s[b];
            int lb = labels[b];
            float esum = 0.f;
#pragma unroll
            for (int j = 0; j < 4; j++) {
                int c0 = cBase + n0 + j * 8 + (lane & 3) * 2;
                if (c0 < Cdim) {   // Cdim even, c0 even -> pair fully valid
                    float cv0 = accC[mt][j][h * 2 + 0];
                    float cv1 = accC[mt][j][h * 2 + 1];
                    float g0 = accG[mt][j][h * 2 + 0];
                    float g1 = accG[mt][j][h * 2 + 1];
                    float w0 = (sbv - cv0) * rsqrtf(fmaxf(2.f - 2.f * g0, EPS_F));
                    float w1 = (sbv - cv1) * rsqrtf(fmaxf(2.f - 2.f * g1, EPS_F));
                    if (c0 == lb) w0 = 0.f;       // dw == 0 exactly in reference
                    if (c0 + 1 == lb) w1 = 0.f;
                    float p0 = MARGIN_F - fminf(MARGIN_F, w0);
                    float p1 = MARGIN_F - fminf(MARGIN_F, w1);
                    float e0 = __expf(SCALE_F * cv0 - SCALE_F);
                    float e1 = __expf(SCALE_F * cv1 - SCALE_F);
                    accC[mt][j][h * 2 + 0] = e0;   // stash ev in registers
                    accC[mt][j][h * 2 + 1] = e1;
                    esum += e0 + e1;
                    *(float2*)&out_pen[(size_t)b * Cdim + c0] = make_float2(p0, p1);
                }
            }
            esum += __shfl_xor_sync(0xffffffffu, esum, 1);
            esum += __shfl_xor_sync(0xffffffffu, esum, 2);
            if ((lane & 3) == 0) atomicAdd(&sRow[row], esum);
        }
    }
    __syncthreads();

    // ---- one global atomic per b per CTA, then grid barrier ----
    if (tid < 128) atomicAdd(&g_rowsum[bBase + tid], sRow[tid]);
    __threadfence();
    __syncthreads();
    if (tid == 0) {
        atomicAdd(&g_count, 1);
        while (*(volatile int*)&g_count < NCTA) { }
    }
    __syncthreads();
    if (tid < 128) sRow[tid] = 1.f / __ldcg(&g_rowsum[bBase + tid]);
    __syncthreads();

    // ---- epilogue part 2: scaled logits ----
#pragma unroll
    for (int mt = 0; mt < 2; mt++) {
#pragma unroll
        for (int h = 0; h < 2; h++) {
            int row = m0 + mt * 16 + h * 8 + (lane >> 2);
            int b = bBase + row;
            float inv = sRow[row];
#pragma unroll
            for (int j = 0; j < 4; j++) {
                int c0 = cBase + n0 + j * 8 + (lane & 3) * 2;
                if (c0 < Cdim) {
                    float e0 = accC[mt][j][h * 2 + 0] * inv;
                    float e1 = accC[mt][j][h * 2 + 1] * inv;
                    *(float2*)&out_logit[(size_t)b * Cdim + c0] =
                        make_float2(e0, e1);
                }
            }
        }
    }
}

// ---------------- launch ----------------
extern "C" void kernel_launch(void* const* d_in, const int* in_sizes, int n_in,
                              void* d_out, int out_size) {
    const float* embds = (const float*)d_in[0];   // [256,128]
    const float* w     = (const float*)d_in[1];   // [128,8000]
    const int* labels  = (const int*)d_in[2];     // [256]
    float* out = (float*)d_out;                   // logits then penalties

    const int kMainSmem = 6 * TILE_U4 * 16;       // 208896 B
    cudaFuncSetAttribute(k_main, cudaFuncAttributeMaxDynamicSharedMemorySize,
                         kMainSmem);

    k_prep<<<Bdim, Ddim>>>(embds, w, labels);

    dim3 g3(CPAD / 128, 2);                       // (63, 2) = 126 CTAs
    k_main<<<g3, NTHR, kMainSmem>>>(out, w, labels);
}